// round 7
// baseline (speedup 1.0000x reference)
#include <cuda_runtime.h>
#include <cuda_bf16.h>
#include <math.h>
#include <stdint.h>

// Problem constants
#define B_   4
#define T_   2048
#define D_   1024
#define H_   16
#define HD_  64
#define NTOK (B_ * T_)   // 8192
#define BH_  (B_ * H_)   // 64

// ---------------------------------------------------------------------------
// Scratch (device globals: allocation-free rule)
// ---------------------------------------------------------------------------
__device__ float g_q[NTOK * D_];
__device__ float g_k[NTOK * D_];
__device__ float g_v[NTOK * D_];
__device__ float g_cos[T_ * 32];
__device__ float g_sin[T_ * 32];
__device__ float g_freqf[16];

// bf16 hi/lo splits for projection GEMMs (A buffers reused: x, then attn out)
__device__ __nv_bfloat16 g_ahi[NTOK * D_];
__device__ __nv_bfloat16 g_alo[NTOK * D_];
__device__ __nv_bfloat16 g_whi[4][D_ * D_];
__device__ __nv_bfloat16 g_wlo[4][D_ * D_];

// head-major bf16 hi/lo for flash attention: [bh][T][HD]
__device__ __nv_bfloat16 g_qhi[BH_ * T_ * HD_];
__device__ __nv_bfloat16 g_qlo[BH_ * T_ * HD_];
__device__ __nv_bfloat16 g_khi[BH_ * T_ * HD_];
__device__ __nv_bfloat16 g_klo[BH_ * T_ * HD_];
__device__ __nv_bfloat16 g_vhi[BH_ * T_ * HD_];
__device__ __nv_bfloat16 g_vlo[BH_ * T_ * HD_];

// ---------------------------------------------------------------------------
// PTX helpers (base compute_103 target: mma.sync / ldmatrix / cp.async only)
// ---------------------------------------------------------------------------
__device__ __forceinline__ uint32_t smem_to_u32(const void* p) {
    uint32_t a;
    asm("{ .reg .u64 t; cvta.to.shared.u64 t, %1; cvt.u32.u64 %0, t; }"
        : "=r"(a) : "l"(p));
    return a;
}

__device__ __forceinline__ void ldsm_x4(uint32_t* r, uint32_t addr) {
    asm volatile("ldmatrix.sync.aligned.m8n8.x4.shared.b16 {%0,%1,%2,%3}, [%4];"
                 : "=r"(r[0]), "=r"(r[1]), "=r"(r[2]), "=r"(r[3]) : "r"(addr));
}

__device__ __forceinline__ void ldsm_x4_t(uint32_t* r, uint32_t addr) {
    asm volatile("ldmatrix.sync.aligned.m8n8.x4.trans.shared.b16 {%0,%1,%2,%3}, [%4];"
                 : "=r"(r[0]), "=r"(r[1]), "=r"(r[2]), "=r"(r[3]) : "r"(addr));
}

__device__ __forceinline__ void mma_bf16(float* c, const uint32_t* a, const uint32_t* b) {
    asm volatile(
        "mma.sync.aligned.m16n8k16.row.col.f32.bf16.bf16.f32 "
        "{%0,%1,%2,%3}, {%4,%5,%6,%7}, {%8,%9}, {%0,%1,%2,%3};"
        : "+f"(c[0]), "+f"(c[1]), "+f"(c[2]), "+f"(c[3])
        : "r"(a[0]), "r"(a[1]), "r"(a[2]), "r"(a[3]), "r"(b[0]), "r"(b[1]));
}

__device__ __forceinline__ void cp_async16(uint32_t dst, const void* src) {
    asm volatile("cp.async.cg.shared.global [%0], [%1], 16;"
                 :: "r"(dst), "l"(src));
}
__device__ __forceinline__ void cp_commit() {
    asm volatile("cp.async.commit_group;" ::: "memory");
}
template <int N>
__device__ __forceinline__ void cp_wait() {
    asm volatile("cp.async.wait_group %0;" :: "n"(N) : "memory");
}

__device__ __forceinline__ uint32_t pack_bf16x2(float lo, float hi) {
    uint32_t r;
    asm("cvt.rn.bf16x2.f32 %0, %1, %2;" : "=r"(r) : "f"(hi), "f"(lo));
    return r;
}

// ---------------------------------------------------------------------------
// fp32 -> (bf16 hi, bf16 lo) split (flat layout)
// ---------------------------------------------------------------------------
__global__ __launch_bounds__(256) void split_kernel(
    const float* __restrict__ src, __nv_bfloat16* __restrict__ hi,
    __nv_bfloat16* __restrict__ lo, int n)
{
    int i4 = (blockIdx.x * blockDim.x + threadIdx.x) * 4;
    if (i4 >= n) return;
    float4 v = *(const float4*)(src + i4);
    __nv_bfloat16 h0 = __float2bfloat16(v.x);
    __nv_bfloat16 h1 = __float2bfloat16(v.y);
    __nv_bfloat16 h2 = __float2bfloat16(v.z);
    __nv_bfloat16 h3 = __float2bfloat16(v.w);
    reinterpret_cast<__nv_bfloat162*>(hi + i4)[0] = __nv_bfloat162(h0, h1);
    reinterpret_cast<__nv_bfloat162*>(hi + i4)[1] = __nv_bfloat162(h2, h3);
    reinterpret_cast<__nv_bfloat162*>(lo + i4)[0] = __nv_bfloat162(
        __float2bfloat16(v.x - __bfloat162float(h0)),
        __float2bfloat16(v.y - __bfloat162float(h1)));
    reinterpret_cast<__nv_bfloat162*>(lo + i4)[1] = __nv_bfloat162(
        __float2bfloat16(v.z - __bfloat162float(h2)),
        __float2bfloat16(v.w - __bfloat162float(h3)));
}

// All 4 weights in one launch
__global__ __launch_bounds__(256) void split_w_kernel(
    const float* __restrict__ w0, const float* __restrict__ w1,
    const float* __restrict__ w2, const float* __restrict__ w3,
    __nv_bfloat16* __restrict__ hi, __nv_bfloat16* __restrict__ lo)
{
    int i4 = (blockIdx.x * blockDim.x + threadIdx.x) * 4;
    if (i4 >= 4 * D_ * D_) return;
    int wi = i4 >> 20;
    int off = i4 & (D_ * D_ - 1);
    const float* src = (wi == 0) ? w0 : (wi == 1) ? w1 : (wi == 2) ? w2 : w3;
    float4 v = *(const float4*)(src + off);
    __nv_bfloat16 h0 = __float2bfloat16(v.x);
    __nv_bfloat16 h1 = __float2bfloat16(v.y);
    __nv_bfloat16 h2 = __float2bfloat16(v.z);
    __nv_bfloat16 h3 = __float2bfloat16(v.w);
    reinterpret_cast<__nv_bfloat162*>(hi + i4)[0] = __nv_bfloat162(h0, h1);
    reinterpret_cast<__nv_bfloat162*>(hi + i4)[1] = __nv_bfloat162(h2, h3);
    reinterpret_cast<__nv_bfloat162*>(lo + i4)[0] = __nv_bfloat162(
        __float2bfloat16(v.x - __bfloat162float(h0)),
        __float2bfloat16(v.y - __bfloat162float(h1)));
    reinterpret_cast<__nv_bfloat162*>(lo + i4)[1] = __nv_bfloat162(
        __float2bfloat16(v.z - __bfloat162float(h2)),
        __float2bfloat16(v.w - __bfloat162float(h3)));
}

// V: token-major fp32 -> head-major bf16 hi/lo
__global__ __launch_bounds__(256) void split_v_kernel() {
    int i4 = (blockIdx.x * blockDim.x + threadIdx.x) * 4;
    if (i4 >= NTOK * D_) return;
    int token = i4 >> 10;
    int rem = i4 & 1023;
    int h = rem >> 6, c = rem & 63;
    int b = token >> 11, t = token & (T_ - 1);
    size_t oi = (((size_t)(b * H_ + h)) * T_ + t) * HD_ + c;
    float4 v = *(const float4*)(g_v + i4);
    __nv_bfloat16 h0 = __float2bfloat16(v.x);
    __nv_bfloat16 h1 = __float2bfloat16(v.y);
    __nv_bfloat16 h2 = __float2bfloat16(v.z);
    __nv_bfloat16 h3 = __float2bfloat16(v.w);
    reinterpret_cast<__nv_bfloat162*>(g_vhi + oi)[0] = __nv_bfloat162(h0, h1);
    reinterpret_cast<__nv_bfloat162*>(g_vhi + oi)[1] = __nv_bfloat162(h2, h3);
    reinterpret_cast<__nv_bfloat162*>(g_vlo + oi)[0] = __nv_bfloat162(
        __float2bfloat16(v.x - __bfloat162float(h0)),
        __float2bfloat16(v.y - __bfloat162float(h1)));
    reinterpret_cast<__nv_bfloat162*>(g_vlo + oi)[1] = __nv_bfloat162(
        __float2bfloat16(v.z - __bfloat162float(h2)),
        __float2bfloat16(v.w - __bfloat162float(h3)));
}

// ---------------------------------------------------------------------------
// mma.sync GEMM, bf16x3 split: C[8192,1024] = A @ W^T
// CTA 256x128, 16 warps (4x4) with 64x32 warp tiles, BK=32, 3-stage ring.
// 512 threads -> 4 warps/SMSP for latency hiding; accum 64 regs/thread.
// ---------------------------------------------------------------------------
#define GM_ROWB   80
#define GM_A_ARR  (256 * GM_ROWB)
#define GM_B_ARR  (128 * GM_ROWB)
#define GM_STAGE  (2 * GM_A_ARR + 2 * GM_B_ARR)
#define GM_SMEM   (3 * GM_STAGE)
#define GM_CHUNKS 32

__device__ __forceinline__ void gm_load_stage(
    uint32_t sbase, const __nv_bfloat16* a_hi, const __nv_bfloat16* a_lo,
    const __nv_bfloat16* b_hi, const __nv_bfloat16* b_lo, int k0, int tid)
{
    int seg = tid & 3;            // 16B segment within 64B row
    int r0  = tid >> 2;           // 0..127
    const __nv_bfloat16* ah = a_hi + k0 + seg * 8;
    const __nv_bfloat16* al = a_lo + k0 + seg * 8;
    const __nv_bfloat16* bh = b_hi + k0 + seg * 8;
    const __nv_bfloat16* bl = b_lo + k0 + seg * 8;
    uint32_t d0 = sbase + seg * 16;
#pragma unroll
    for (int rr = 0; rr < 2; rr++) {
        int row = r0 + rr * 128;
        cp_async16(d0 + row * GM_ROWB, ah + (size_t)row * D_);
        cp_async16(d0 + GM_A_ARR + row * GM_ROWB, al + (size_t)row * D_);
    }
    cp_async16(d0 + 2 * GM_A_ARR + r0 * GM_ROWB, bh + (size_t)r0 * D_);
    cp_async16(d0 + 2 * GM_A_ARR + GM_B_ARR + r0 * GM_ROWB, bl + (size_t)r0 * D_);
}

__global__ __launch_bounds__(512, 1) void gemm_mma_kernel(
    const __nv_bfloat16* __restrict__ Ahi, const __nv_bfloat16* __restrict__ Alo,
    const __nv_bfloat16* __restrict__ Whi, const __nv_bfloat16* __restrict__ Wlo,
    int wbase, float* C0, float* C1, float* C2)
{
    extern __shared__ __align__(128) char smem[];
    uint32_t sb = smem_to_u32(smem);

    const int tid  = threadIdx.x;
    const int wid  = tid >> 5;
    const int lane = tid & 31;
    const int wm = wid & 3;       // 4 warp rows of 64
    const int wn = wid >> 2;      // 4 warp cols of 32
    const int bm = blockIdx.y * 256;
    const int bn = blockIdx.x * 128;
    const int z  = blockIdx.z;

    float* C = (z == 0) ? C0 : (z == 1) ? C1 : C2;
    const __nv_bfloat16* a_hi = Ahi + (size_t)bm * D_;
    const __nv_bfloat16* a_lo = Alo + (size_t)bm * D_;
    const __nv_bfloat16* b_hi = Whi + (size_t)(wbase + z) * D_ * D_ + (size_t)bn * D_;
    const __nv_bfloat16* b_lo = Wlo + (size_t)(wbase + z) * D_ * D_ + (size_t)bn * D_;

    float c[4][4][4];
#pragma unroll
    for (int mt = 0; mt < 4; mt++)
#pragma unroll
        for (int nt = 0; nt < 4; nt++)
#pragma unroll
            for (int r = 0; r < 4; r++) c[mt][nt][r] = 0.0f;

    const int rowA = lane & 15;
    const int kbA  = lane >> 4;
    const int rowB = (lane & 7) + ((lane >> 4) << 3);
    const int kbB  = (lane >> 3) & 1;
    const uint32_t aoff = (uint32_t)(wm * 64 + rowA) * GM_ROWB + kbA * 16;
    const uint32_t boff = (uint32_t)(wn * 32 + rowB) * GM_ROWB + kbB * 16;

    gm_load_stage(sb, a_hi, a_lo, b_hi, b_lo, 0, tid);
    cp_commit();
    gm_load_stage(sb + GM_STAGE, a_hi, a_lo, b_hi, b_lo, 32, tid);
    cp_commit();

    int stage = 0;
    for (int i = 0; i < GM_CHUNKS; i++) {
        if (i < GM_CHUNKS - 1) cp_wait<1>(); else cp_wait<0>();
        __syncthreads();
        if (i + 2 < GM_CHUNKS) {
            int ns = (stage + 2 >= 3) ? stage - 1 : stage + 2;
            gm_load_stage(sb + ns * GM_STAGE, a_hi, a_lo, b_hi, b_lo, (i + 2) * 32, tid);
            cp_commit();
        }
        uint32_t st = sb + stage * GM_STAGE;

#pragma unroll
        for (int ks = 0; ks < 2; ks++) {
            uint32_t koff = ks * 32;
            uint32_t fah[4][4], fal[4][4];
#pragma unroll
            for (int mt = 0; mt < 4; mt++) {
                ldsm_x4(fah[mt], st + aoff + koff + mt * 16 * GM_ROWB);
                ldsm_x4(fal[mt], st + GM_A_ARR + aoff + koff + mt * 16 * GM_ROWB);
            }
#pragma unroll
            for (int np = 0; np < 2; np++) {
                uint32_t fbh[4], fbl[4];
                ldsm_x4(fbh, st + 2 * GM_A_ARR + boff + koff + np * 16 * GM_ROWB);
                ldsm_x4(fbl, st + 2 * GM_A_ARR + GM_B_ARR + boff + koff + np * 16 * GM_ROWB);
#pragma unroll
                for (int mt = 0; mt < 4; mt++) {
#pragma unroll
                    for (int half = 0; half < 2; half++) {
                        float* cc = c[mt][np * 2 + half];
                        mma_bf16(cc, fah[mt], fbh + half * 2);
                        mma_bf16(cc, fal[mt], fbh + half * 2);
                        mma_bf16(cc, fah[mt], fbl + half * 2);
                    }
                }
            }
        }
        stage = (stage + 1 >= 3) ? 0 : stage + 1;
    }

    const int erow = bm + wm * 64 + (lane >> 2);
    const int ecol = bn + wn * 32 + (lane & 3) * 2;
#pragma unroll
    for (int mt = 0; mt < 4; mt++)
#pragma unroll
        for (int nt = 0; nt < 4; nt++) {
            int r0 = erow + mt * 16;
            int cc = ecol + nt * 8;
            *(float2*)&C[(size_t)r0 * D_ + cc]       = make_float2(c[mt][nt][0], c[mt][nt][1]);
            *(float2*)&C[(size_t)(r0 + 8) * D_ + cc] = make_float2(c[mt][nt][2], c[mt][nt][3]);
        }
}

// ---------------------------------------------------------------------------
// RoPE tables: fp64 pow on 16 threads only; table uses fp32 Cody-Waite + MUFU.
// ---------------------------------------------------------------------------
__global__ void rope_freq_kernel() {
    int j = threadIdx.x;
    if (j < 16) g_freqf[j] = (float)pow(1.0 / 1024.0, (double)j / 15.0);
}

__global__ __launch_bounds__(256) void rope_tables_kernel() {
    int i = blockIdx.x * blockDim.x + threadIdx.x;
    if (i >= T_ * 32) return;
    int t = i >> 5;
    int j = i & 31;
    if (j >= 16) { g_cos[i] = 1.0f; g_sin[i] = 0.0f; return; }
    float theta = (float)t * g_freqf[j];
    const float inv2pi = 0.15915494309189535f;
    const float c1 = 6.28125f;
    const float c2 = 1.9345283508300781e-3f;
    const float c3 = 7.7882876e-7f;
    float n = rintf(theta * inv2pi);
    float r = fmaf(-n, c1, theta);
    r = fmaf(-n, c2, r);
    r = fmaf(-n, c3, r);
    g_cos[i] = cosf(r);
    g_sin[i] = sinf(r);
}

// ---------------------------------------------------------------------------
// Fused per-head RMSNorm + RoPE; writes head-major bf16 hi/lo.
// Q scaled by 0.125 * log2(e): flash softmax runs in exp2 domain.
// ---------------------------------------------------------------------------
#define QSCALE (0.125f * 1.4426950408889634f)

__global__ __launch_bounds__(256) void norm_rope_kernel() {
    int gw   = (blockIdx.x * blockDim.x + threadIdx.x) >> 5;
    int lane = threadIdx.x & 31;
    if (gw >= NTOK * H_) return;

    int token = gw >> 4;
    int h = gw & 15;
    int b = token >> 11;
    int t = token & (T_ - 1);
    size_t base = (size_t)gw * 64;
    size_t hb = (((size_t)(b * H_ + h)) * T_ + t) * HD_;

    float c = g_cos[t * 32 + lane];
    float s = g_sin[t * 32 + lane];

    {   // Q
        float a  = g_q[base + lane];
        float b2 = g_q[base + lane + 32];
        float ss = a * a + b2 * b2;
#pragma unroll
        for (int m = 16; m > 0; m >>= 1) ss += __shfl_xor_sync(0xffffffffu, ss, m);
        float r = rsqrtf(ss * (1.0f / 64.0f) + 1e-6f);
        a *= r; b2 *= r;
        float y1 = (a * c + b2 * s) * QSCALE;
        float y2 = (-a * s + b2 * c) * QSCALE;
        __nv_bfloat16 h1 = __float2bfloat16(y1);
        __nv_bfloat16 h2 = __float2bfloat16(y2);
        g_qhi[hb + lane]      = h1;
        g_qhi[hb + lane + 32] = h2;
        g_qlo[hb + lane]      = __float2bfloat16(y1 - __bfloat162float(h1));
        g_qlo[hb + lane + 32] = __float2bfloat16(y2 - __bfloat162float(h2));
    }
    {   // K
        float a  = g_k[base + lane];
        float b2 = g_k[base + lane + 32];
        float ss = a * a + b2 * b2;
#pragma unroll
        for (int m = 16; m > 0; m >>= 1) ss += __shfl_xor_sync(0xffffffffu, ss, m);
        float r = rsqrtf(ss * (1.0f / 64.0f) + 1e-6f);
        a *= r; b2 *= r;
        float y1 = a * c + b2 * s;
        float y2 = -a * s + b2 * c;
        __nv_bfloat16 h1 = __float2bfloat16(y1);
        __nv_bfloat16 h2 = __float2bfloat16(y2);
        g_khi[hb + lane]      = h1;
        g_khi[hb + lane + 32] = h2;
        g_klo[hb + lane]      = __float2bfloat16(y1 - __bfloat162float(h1));
        g_klo[hb + lane + 32] = __float2bfloat16(y2 - __bfloat162float(h2));
    }
}

// ---------------------------------------------------------------------------
// Flash attention via mma.sync, bf16x3 (causal). 128x128 tiles, exp2 softmax.
// Epilogue writes bf16 hi/lo split directly (token-major) for the wo GEMM.
// ---------------------------------------------------------------------------
#define FROWB   144u
#define FQ_SIZE (128 * 144)
#define FKV_OFF (2 * FQ_SIZE)
#define FKV_ARR (128 * 144)
#define FSTAGE  (4 * FKV_ARR)
#define FMMA_SMEM (FKV_OFF + 2 * FSTAGE)   // 184320

__device__ __forceinline__ void f_load_kv(
    uint32_t dst, const __nv_bfloat16* kh, const __nv_bfloat16* kl,
    const __nv_bfloat16* vh, const __nv_bfloat16* vl, size_t goff, int tid)
{
    const __nv_bfloat16* srcs[4] = {kh, kl, vh, vl};
    int seg = tid & 7, r0 = tid >> 3;
#pragma unroll
    for (int arr = 0; arr < 4; arr++) {
        const __nv_bfloat16* s = srcs[arr] + goff + seg * 8;
        uint32_t d = dst + arr * FKV_ARR + seg * 16;
#pragma unroll
        for (int rr = 0; rr < 4; rr++) {
            int row = r0 + rr * 32;
            cp_async16(d + row * FROWB, s + row * HD_);
        }
    }
}

__global__ __launch_bounds__(256, 1) void flash_mma_kernel(
    const __nv_bfloat16* __restrict__ Qhi, const __nv_bfloat16* __restrict__ Qlo,
    const __nv_bfloat16* __restrict__ Khi, const __nv_bfloat16* __restrict__ Klo,
    const __nv_bfloat16* __restrict__ Vhi, const __nv_bfloat16* __restrict__ Vlo,
    __nv_bfloat16* __restrict__ Ohi, __nv_bfloat16* __restrict__ Olo)
{
    extern __shared__ __align__(128) char fsm[];
    uint32_t sb = smem_to_u32(fsm);
    const int tid = threadIdx.x, wid = tid >> 5, lane = tid & 31;
    const int bh = blockIdx.x;
    const int qt = 15 - blockIdx.y;
    const int b = bh >> 4, h = bh & 15;
    const size_t headoff = (size_t)bh * T_ * HD_;
    const int nkt = qt + 1;

    {
        int seg = tid & 7, r0 = tid >> 3;
        const __nv_bfloat16* q0 = Qhi + headoff + (size_t)qt * 128 * HD_ + seg * 8;
        const __nv_bfloat16* q1 = Qlo + headoff + (size_t)qt * 128 * HD_ + seg * 8;
#pragma unroll
        for (int rr = 0; rr < 4; rr++) {
            int row = r0 + rr * 32;
            cp_async16(sb + row * FROWB + seg * 16, q0 + row * HD_);
            cp_async16(sb + FQ_SIZE + row * FROWB + seg * 16, q1 + row * HD_);
        }
    }
    f_load_kv(sb + FKV_OFF, Khi, Klo, Vhi, Vlo, headoff, tid);
    cp_commit();

    uint32_t fqh[4][4], fql[4][4];
    float o[8][4];
#pragma unroll
    for (int nt = 0; nt < 8; nt++)
#pragma unroll
        for (int r = 0; r < 4; r++) o[nt][r] = 0.0f;
    float m0 = -1e30f, m1 = -1e30f, l0 = 0.0f, l1 = 0.0f;

    const uint32_t qrow_off = (uint32_t)(wid * 16 + (lane & 15)) * FROWB + (lane >> 4) * 16;
    const uint32_t krow_off = (uint32_t)((lane & 7) + ((lane >> 4) << 3)) * FROWB
                              + ((lane >> 3) & 1) * 16;
    const uint32_t vrow_off = (uint32_t)(lane & 15) * FROWB + (lane >> 4) * 16;

    for (int jt = 0; jt < nkt; jt++) {
        if (jt + 1 < nkt) {
            f_load_kv(sb + FKV_OFF + ((jt + 1) & 1) * FSTAGE, Khi, Klo, Vhi, Vlo,
                      headoff + (size_t)(jt + 1) * 128 * HD_, tid);
            cp_commit();
            cp_wait<1>();
        } else {
            cp_wait<0>();
        }
        __syncthreads();

        if (jt == 0) {
#pragma unroll
            for (int ks = 0; ks < 4; ks++) {
                ldsm_x4(fqh[ks], sb + qrow_off + ks * 32);
                ldsm_x4(fql[ks], sb + FQ_SIZE + qrow_off + ks * 32);
            }
        }

        uint32_t st = sb + FKV_OFF + (jt & 1) * FSTAGE;

        float s[16][4];
#pragma unroll
        for (int nt = 0; nt < 16; nt++)
#pragma unroll
            for (int r = 0; r < 4; r++) s[nt][r] = 0.0f;

#pragma unroll
        for (int np = 0; np < 8; np++) {
#pragma unroll
            for (int ks = 0; ks < 4; ks++) {
                uint32_t addr = st + krow_off + np * 16 * FROWB + ks * 32;
                uint32_t fk[4];
                ldsm_x4(fk, addr);
                mma_bf16(s[2 * np],     fqh[ks], fk + 0);
                mma_bf16(s[2 * np + 1], fqh[ks], fk + 2);
                mma_bf16(s[2 * np],     fql[ks], fk + 0);
                mma_bf16(s[2 * np + 1], fql[ks], fk + 2);
                ldsm_x4(fk, addr + FKV_ARR);
                mma_bf16(s[2 * np],     fqh[ks], fk + 0);
                mma_bf16(s[2 * np + 1], fqh[ks], fk + 2);
            }
        }

        if (jt == qt) {
            int grow = qt * 128 + wid * 16 + (lane >> 2);
            int gc0 = jt * 128 + (lane & 3) * 2;
#pragma unroll
            for (int nt = 0; nt < 16; nt++) {
                int cc = gc0 + nt * 8;
                if (cc > grow)          s[nt][0] = -1e30f;
                if (cc + 1 > grow)      s[nt][1] = -1e30f;
                if (cc > grow + 8)      s[nt][2] = -1e30f;
                if (cc + 1 > grow + 8)  s[nt][3] = -1e30f;
            }
        }

        float mx0 = -1e30f, mx1 = -1e30f;
#pragma unroll
        for (int nt = 0; nt < 16; nt++) {
            mx0 = fmaxf(mx0, fmaxf(s[nt][0], s[nt][1]));
            mx1 = fmaxf(mx1, fmaxf(s[nt][2], s[nt][3]));
        }
        mx0 = fmaxf(mx0, __shfl_xor_sync(0xffffffffu, mx0, 1));
        mx0 = fmaxf(mx0, __shfl_xor_sync(0xffffffffu, mx0, 2));
        mx1 = fmaxf(mx1, __shfl_xor_sync(0xffffffffu, mx1, 1));
        mx1 = fmaxf(mx1, __shfl_xor_sync(0xffffffffu, mx1, 2));
        float mn0 = fmaxf(m0, mx0), mn1 = fmaxf(m1, mx1);
        float al0 = exp2f(m0 - mn0), al1 = exp2f(m1 - mn1);
        float rs0 = 0.0f, rs1 = 0.0f;
#pragma unroll
        for (int nt = 0; nt < 16; nt++) {
            s[nt][0] = exp2f(s[nt][0] - mn0);
            s[nt][1] = exp2f(s[nt][1] - mn0);
            s[nt][2] = exp2f(s[nt][2] - mn1);
            s[nt][3] = exp2f(s[nt][3] - mn1);
            rs0 += s[nt][0] + s[nt][1];
            rs1 += s[nt][2] + s[nt][3];
        }
        rs0 += __shfl_xor_sync(0xffffffffu, rs0, 1);
        rs0 += __shfl_xor_sync(0xffffffffu, rs0, 2);
        rs1 += __shfl_xor_sync(0xffffffffu, rs1, 1);
        rs1 += __shfl_xor_sync(0xffffffffu, rs1, 2);
        l0 = l0 * al0 + rs0; m0 = mn0;
        l1 = l1 * al1 + rs1; m1 = mn1;
#pragma unroll
        for (int nt = 0; nt < 8; nt++) {
            o[nt][0] *= al0; o[nt][1] *= al0;
            o[nt][2] *= al1; o[nt][3] *= al1;
        }

        uint32_t fph[8][4], fpl[8][4];
#pragma unroll
        for (int f = 0; f < 8; f++) {
#pragma unroll
            for (int half = 0; half < 2; half++) {
                int nt = 2 * f + half;
#pragma unroll
                for (int rh = 0; rh < 2; rh++) {
                    float p0 = s[nt][rh * 2], p1 = s[nt][rh * 2 + 1];
                    uint32_t hi = pack_bf16x2(p0, p1);
                    float h0 = __uint_as_float(hi << 16);
                    float h1 = __uint_as_float(hi & 0xFFFF0000u);
                    uint32_t lo = pack_bf16x2(p0 - h0, p1 - h1);
                    fph[f][half * 2 + rh] = hi;
                    fpl[f][half * 2 + rh] = lo;
                }
            }
        }

#pragma unroll
        for (int nh = 0; nh < 4; nh++) {
#pragma unroll
            for (int ks = 0; ks < 8; ks++) {
                uint32_t addr = st + 2 * FKV_ARR + vrow_off + ks * 16 * FROWB + nh * 32;
                uint32_t fv[4];
                ldsm_x4_t(fv, addr);
                mma_bf16(o[2 * nh],     fph[ks], fv + 0);
                mma_bf16(o[2 * nh + 1], fph[ks], fv + 2);
                mma_bf16(o[2 * nh],     fpl[ks], fv + 0);
                mma_bf16(o[2 * nh + 1], fpl[ks], fv + 2);
                ldsm_x4_t(fv, addr + FKV_ARR);
                mma_bf16(o[2 * nh],     fph[ks], fv + 0);
                mma_bf16(o[2 * nh + 1], fph[ks], fv + 2);
            }
        }
        __syncthreads();
    }

    // epilogue: normalize + bf16 hi/lo split, token-major [b][t][h*64+hd]
    float inv0 = 1.0f / l0, inv1 = 1.0f / l1;
    int row = qt * 128 + wid * 16 + (lane >> 2);
    size_t base0 = ((size_t)b * T_ + row) * D_ + h * 64 + (lane & 3) * 2;
    size_t base1 = base0 + (size_t)8 * D_;
#pragma unroll
    for (int nt = 0; nt < 8; nt++) {
        float v0 = o[nt][0] * inv0, v1 = o[nt][1] * inv0;
        float v2 = o[nt][2] * inv1, v3 = o[nt][3] * inv1;
        __nv_bfloat16 h0 = __float2bfloat16(v0), h1 = __float2bfloat16(v1);
        __nv_bfloat16 h2 = __float2bfloat16(v2), h3 = __float2bfloat16(v3);
        *reinterpret_cast<__nv_bfloat162*>(Ohi + base0 + nt * 8) = __nv_bfloat162(h0, h1);
        *reinterpret_cast<__nv_bfloat162*>(Ohi + base1 + nt * 8) = __nv_bfloat162(h2, h3);
        *reinterpret_cast<__nv_bfloat162*>(Olo + base0 + nt * 8) = __nv_bfloat162(
            __float2bfloat16(v0 - __bfloat162float(h0)),
            __float2bfloat16(v1 - __bfloat162float(h1)));
        *reinterpret_cast<__nv_bfloat162*>(Olo + base1 + nt * 8) = __nv_bfloat162(
            __float2bfloat16(v2 - __bfloat162float(h2)),
            __float2bfloat16(v3 - __bfloat162float(h3)));
    }
}

// ---------------------------------------------------------------------------
// Launch
// ---------------------------------------------------------------------------
extern "C" void kernel_launch(void* const* d_in, const int* in_sizes, int n_in,
                              void* d_out, int out_size)
{
    (void)in_sizes; (void)n_in; (void)out_size;
    const float* x  = (const float*)d_in[0];
    const float* w[4] = {(const float*)d_in[1], (const float*)d_in[2],
                         (const float*)d_in[3], (const float*)d_in[4]};
    float* out = (float*)d_out;

    float *qp, *kp, *vp;
    __nv_bfloat16 *ahi, *alo, *whi, *wlo;
    __nv_bfloat16 *qhi, *qlo, *khi, *klo, *vhi, *vlo;
    cudaGetSymbolAddress((void**)&qp, g_q);
    cudaGetSymbolAddress((void**)&kp, g_k);
    cudaGetSymbolAddress((void**)&vp, g_v);
    cudaGetSymbolAddress((void**)&ahi, g_ahi);
    cudaGetSymbolAddress((void**)&alo, g_alo);
    cudaGetSymbolAddress((void**)&whi, g_whi);
    cudaGetSymbolAddress((void**)&wlo, g_wlo);
    cudaGetSymbolAddress((void**)&qhi, g_qhi);
    cudaGetSymbolAddress((void**)&qlo, g_qlo);
    cudaGetSymbolAddress((void**)&khi, g_khi);
    cudaGetSymbolAddress((void**)&klo, g_klo);
    cudaGetSymbolAddress((void**)&vhi, g_vhi);
    cudaGetSymbolAddress((void**)&vlo, g_vlo);

    cudaFuncSetAttribute(gemm_mma_kernel,
                         cudaFuncAttributeMaxDynamicSharedMemorySize, GM_SMEM);
    cudaFuncSetAttribute(flash_mma_kernel,
                         cudaFuncAttributeMaxDynamicSharedMemorySize, FMMA_SMEM);

    rope_freq_kernel<<<1, 16>>>();
    rope_tables_kernel<<<(T_ * 32 + 255) / 256, 256>>>();

    split_kernel<<<(NTOK * D_ / 4 + 255) / 256, 256>>>(x, ahi, alo, NTOK * D_);
    split_w_kernel<<<(4 * D_ * D_ / 4 + 255) / 256, 256>>>(
        w[0], w[1], w[2], w[3], whi, wlo);

    gemm_mma_kernel<<<dim3(D_ / 128, NTOK / 256, 3), 512, GM_SMEM>>>(
        ahi, alo, whi, wlo, 0, qp, kp, vp);

    norm_rope_kernel<<<(NTOK * H_) / 8, 256>>>();
    split_v_kernel<<<(NTOK * D_ / 4 + 255) / 256, 256>>>();

    // flash writes bf16 hi/lo attention output directly into the A buffers
    flash_mma_kernel<<<dim3(BH_, T_ / 128), 256, FMMA_SMEM>>>(
        qhi, qlo, khi, klo, vhi, vlo, ahi, alo);

    gemm_mma_kernel<<<dim3(D_ / 128, NTOK / 256, 1), 512, GM_SMEM>>>(
        ahi, alo, whi, wlo, 3, out, out, out);
}

// round 8
// speedup vs baseline: 1.5283x; 1.5283x over previous
#include <cuda_runtime.h>
#include <cuda_bf16.h>
#include <math.h>
#include <stdint.h>

// Problem constants
#define B_   4
#define T_   2048
#define D_   1024
#define H_   16
#define HD_  64
#define NTOK (B_ * T_)   // 8192
#define BH_  (B_ * H_)   // 64

// ---------------------------------------------------------------------------
// Scratch (device globals: allocation-free rule)
// ---------------------------------------------------------------------------
__device__ float g_q[NTOK * D_];
__device__ float g_k[NTOK * D_];
__device__ float g_v[NTOK * D_];
__device__ float g_cos[T_ * 32];
__device__ float g_sin[T_ * 32];
__device__ float g_freqf[16];

// bf16 hi/lo splits for projection GEMMs (A buffers reused: x, then attn out)
__device__ __nv_bfloat16 g_ahi[NTOK * D_];
__device__ __nv_bfloat16 g_alo[NTOK * D_];
__device__ __nv_bfloat16 g_whi[4][D_ * D_];
__device__ __nv_bfloat16 g_wlo[4][D_ * D_];

// head-major bf16 hi/lo for flash attention: [bh][T][HD]
__device__ __nv_bfloat16 g_qhi[BH_ * T_ * HD_];
__device__ __nv_bfloat16 g_qlo[BH_ * T_ * HD_];
__device__ __nv_bfloat16 g_khi[BH_ * T_ * HD_];
__device__ __nv_bfloat16 g_klo[BH_ * T_ * HD_];
__device__ __nv_bfloat16 g_vhi[BH_ * T_ * HD_];
__device__ __nv_bfloat16 g_vlo[BH_ * T_ * HD_];

// ---------------------------------------------------------------------------
// PTX helpers (base compute_103 target: mma.sync / ldmatrix / cp.async only)
// ---------------------------------------------------------------------------
__device__ __forceinline__ uint32_t smem_to_u32(const void* p) {
    uint32_t a;
    asm("{ .reg .u64 t; cvta.to.shared.u64 t, %1; cvt.u32.u64 %0, t; }"
        : "=r"(a) : "l"(p));
    return a;
}

__device__ __forceinline__ void ldsm_x4(uint32_t* r, uint32_t addr) {
    asm volatile("ldmatrix.sync.aligned.m8n8.x4.shared.b16 {%0,%1,%2,%3}, [%4];"
                 : "=r"(r[0]), "=r"(r[1]), "=r"(r[2]), "=r"(r[3]) : "r"(addr));
}

__device__ __forceinline__ void ldsm_x4_t(uint32_t* r, uint32_t addr) {
    asm volatile("ldmatrix.sync.aligned.m8n8.x4.trans.shared.b16 {%0,%1,%2,%3}, [%4];"
                 : "=r"(r[0]), "=r"(r[1]), "=r"(r[2]), "=r"(r[3]) : "r"(addr));
}

__device__ __forceinline__ void mma_bf16(float* c, const uint32_t* a, const uint32_t* b) {
    asm volatile(
        "mma.sync.aligned.m16n8k16.row.col.f32.bf16.bf16.f32 "
        "{%0,%1,%2,%3}, {%4,%5,%6,%7}, {%8,%9}, {%0,%1,%2,%3};"
        : "+f"(c[0]), "+f"(c[1]), "+f"(c[2]), "+f"(c[3])
        : "r"(a[0]), "r"(a[1]), "r"(a[2]), "r"(a[3]), "r"(b[0]), "r"(b[1]));
}

__device__ __forceinline__ void cp_async16(uint32_t dst, const void* src) {
    asm volatile("cp.async.cg.shared.global [%0], [%1], 16;"
                 :: "r"(dst), "l"(src));
}
__device__ __forceinline__ void cp_commit() {
    asm volatile("cp.async.commit_group;" ::: "memory");
}
template <int N>
__device__ __forceinline__ void cp_wait() {
    asm volatile("cp.async.wait_group %0;" :: "n"(N) : "memory");
}

__device__ __forceinline__ uint32_t pack_bf16x2(float lo, float hi) {
    uint32_t r;
    asm("cvt.rn.bf16x2.f32 %0, %1, %2;" : "=r"(r) : "f"(hi), "f"(lo));
    return r;
}

// ---------------------------------------------------------------------------
// fp32 -> (bf16 hi, bf16 lo) split (flat layout)
// ---------------------------------------------------------------------------
__global__ __launch_bounds__(256) void split_kernel(
    const float* __restrict__ src, __nv_bfloat16* __restrict__ hi,
    __nv_bfloat16* __restrict__ lo, int n)
{
    int i4 = (blockIdx.x * blockDim.x + threadIdx.x) * 4;
    if (i4 >= n) return;
    float4 v = *(const float4*)(src + i4);
    __nv_bfloat16 h0 = __float2bfloat16(v.x);
    __nv_bfloat16 h1 = __float2bfloat16(v.y);
    __nv_bfloat16 h2 = __float2bfloat16(v.z);
    __nv_bfloat16 h3 = __float2bfloat16(v.w);
    reinterpret_cast<__nv_bfloat162*>(hi + i4)[0] = __nv_bfloat162(h0, h1);
    reinterpret_cast<__nv_bfloat162*>(hi + i4)[1] = __nv_bfloat162(h2, h3);
    reinterpret_cast<__nv_bfloat162*>(lo + i4)[0] = __nv_bfloat162(
        __float2bfloat16(v.x - __bfloat162float(h0)),
        __float2bfloat16(v.y - __bfloat162float(h1)));
    reinterpret_cast<__nv_bfloat162*>(lo + i4)[1] = __nv_bfloat162(
        __float2bfloat16(v.z - __bfloat162float(h2)),
        __float2bfloat16(v.w - __bfloat162float(h3)));
}

// All 4 weights in one launch
__global__ __launch_bounds__(256) void split_w_kernel(
    const float* __restrict__ w0, const float* __restrict__ w1,
    const float* __restrict__ w2, const float* __restrict__ w3,
    __nv_bfloat16* __restrict__ hi, __nv_bfloat16* __restrict__ lo)
{
    int i4 = (blockIdx.x * blockDim.x + threadIdx.x) * 4;
    if (i4 >= 4 * D_ * D_) return;
    int wi = i4 >> 20;
    int off = i4 & (D_ * D_ - 1);
    const float* src = (wi == 0) ? w0 : (wi == 1) ? w1 : (wi == 2) ? w2 : w3;
    float4 v = *(const float4*)(src + off);
    __nv_bfloat16 h0 = __float2bfloat16(v.x);
    __nv_bfloat16 h1 = __float2bfloat16(v.y);
    __nv_bfloat16 h2 = __float2bfloat16(v.z);
    __nv_bfloat16 h3 = __float2bfloat16(v.w);
    reinterpret_cast<__nv_bfloat162*>(hi + i4)[0] = __nv_bfloat162(h0, h1);
    reinterpret_cast<__nv_bfloat162*>(hi + i4)[1] = __nv_bfloat162(h2, h3);
    reinterpret_cast<__nv_bfloat162*>(lo + i4)[0] = __nv_bfloat162(
        __float2bfloat16(v.x - __bfloat162float(h0)),
        __float2bfloat16(v.y - __bfloat162float(h1)));
    reinterpret_cast<__nv_bfloat162*>(lo + i4)[1] = __nv_bfloat162(
        __float2bfloat16(v.z - __bfloat162float(h2)),
        __float2bfloat16(v.w - __bfloat162float(h3)));
}

// V: token-major fp32 -> head-major bf16 hi/lo
__global__ __launch_bounds__(256) void split_v_kernel() {
    int i4 = (blockIdx.x * blockDim.x + threadIdx.x) * 4;
    if (i4 >= NTOK * D_) return;
    int token = i4 >> 10;
    int rem = i4 & 1023;
    int h = rem >> 6, c = rem & 63;
    int b = token >> 11, t = token & (T_ - 1);
    size_t oi = (((size_t)(b * H_ + h)) * T_ + t) * HD_ + c;
    float4 v = *(const float4*)(g_v + i4);
    __nv_bfloat16 h0 = __float2bfloat16(v.x);
    __nv_bfloat16 h1 = __float2bfloat16(v.y);
    __nv_bfloat16 h2 = __float2bfloat16(v.z);
    __nv_bfloat16 h3 = __float2bfloat16(v.w);
    reinterpret_cast<__nv_bfloat162*>(g_vhi + oi)[0] = __nv_bfloat162(h0, h1);
    reinterpret_cast<__nv_bfloat162*>(g_vhi + oi)[1] = __nv_bfloat162(h2, h3);
    reinterpret_cast<__nv_bfloat162*>(g_vlo + oi)[0] = __nv_bfloat162(
        __float2bfloat16(v.x - __bfloat162float(h0)),
        __float2bfloat16(v.y - __bfloat162float(h1)));
    reinterpret_cast<__nv_bfloat162*>(g_vlo + oi)[1] = __nv_bfloat162(
        __float2bfloat16(v.z - __bfloat162float(h2)),
        __float2bfloat16(v.w - __bfloat162float(h3)));
}

// ---------------------------------------------------------------------------
// mma.sync GEMM, bf16x3 split: C[8192,1024] = A @ W^T  (R6 configuration:
// CTA 256x128, 8 warps (4x2) with 64x64 warp tiles, BK=32, 3-stage ring,
// 256 threads.)
// ---------------------------------------------------------------------------
#define GM_ROWB   80
#define GM_A_ARR  (256 * GM_ROWB)
#define GM_B_ARR  (128 * GM_ROWB)
#define GM_STAGE  (2 * GM_A_ARR + 2 * GM_B_ARR)
#define GM_SMEM   (3 * GM_STAGE)
#define GM_CHUNKS 32

__device__ __forceinline__ void gm_load_stage(
    uint32_t sbase, const __nv_bfloat16* a_hi, const __nv_bfloat16* a_lo,
    const __nv_bfloat16* b_hi, const __nv_bfloat16* b_lo, int k0, int tid)
{
    int seg = tid & 3;
    int r0  = tid >> 2;
    const __nv_bfloat16* ah = a_hi + k0 + seg * 8;
    const __nv_bfloat16* al = a_lo + k0 + seg * 8;
    const __nv_bfloat16* bh = b_hi + k0 + seg * 8;
    const __nv_bfloat16* bl = b_lo + k0 + seg * 8;
    uint32_t d0 = sbase + seg * 16;
#pragma unroll
    for (int rr = 0; rr < 4; rr++) {
        int row = r0 + rr * 64;
        cp_async16(d0 + row * GM_ROWB, ah + (size_t)row * D_);
        cp_async16(d0 + GM_A_ARR + row * GM_ROWB, al + (size_t)row * D_);
    }
#pragma unroll
    for (int rr = 0; rr < 2; rr++) {
        int row = r0 + rr * 64;
        cp_async16(d0 + 2 * GM_A_ARR + row * GM_ROWB, bh + (size_t)row * D_);
        cp_async16(d0 + 2 * GM_A_ARR + GM_B_ARR + row * GM_ROWB, bl + (size_t)row * D_);
    }
}

__global__ __launch_bounds__(256, 1) void gemm_mma_kernel(
    const __nv_bfloat16* __restrict__ Ahi, const __nv_bfloat16* __restrict__ Alo,
    const __nv_bfloat16* __restrict__ Whi, const __nv_bfloat16* __restrict__ Wlo,
    int wbase, float* C0, float* C1, float* C2)
{
    extern __shared__ __align__(128) char smem[];
    uint32_t sb = smem_to_u32(smem);

    const int tid  = threadIdx.x;
    const int wid  = tid >> 5;
    const int lane = tid & 31;
    const int wm = wid & 3;
    const int wn = wid >> 2;
    const int bm = blockIdx.y * 256;
    const int bn = blockIdx.x * 128;
    const int z  = blockIdx.z;

    float* C = (z == 0) ? C0 : (z == 1) ? C1 : C2;
    const __nv_bfloat16* a_hi = Ahi + (size_t)bm * D_;
    const __nv_bfloat16* a_lo = Alo + (size_t)bm * D_;
    const __nv_bfloat16* b_hi = Whi + (size_t)(wbase + z) * D_ * D_ + (size_t)bn * D_;
    const __nv_bfloat16* b_lo = Wlo + (size_t)(wbase + z) * D_ * D_ + (size_t)bn * D_;

    float c[4][8][4];
#pragma unroll
    for (int mt = 0; mt < 4; mt++)
#pragma unroll
        for (int nt = 0; nt < 8; nt++)
#pragma unroll
            for (int r = 0; r < 4; r++) c[mt][nt][r] = 0.0f;

    const int rowA = lane & 15;
    const int kbA  = lane >> 4;
    const int rowB = (lane & 7) + ((lane >> 4) << 3);
    const int kbB  = (lane >> 3) & 1;
    const uint32_t aoff = (uint32_t)(wm * 64 + rowA) * GM_ROWB + kbA * 16;
    const uint32_t boff = (uint32_t)(wn * 64 + rowB) * GM_ROWB + kbB * 16;

    gm_load_stage(sb, a_hi, a_lo, b_hi, b_lo, 0, tid);
    cp_commit();
    gm_load_stage(sb + GM_STAGE, a_hi, a_lo, b_hi, b_lo, 32, tid);
    cp_commit();

    int stage = 0;
    for (int i = 0; i < GM_CHUNKS; i++) {
        if (i < GM_CHUNKS - 1) cp_wait<1>(); else cp_wait<0>();
        __syncthreads();
        if (i + 2 < GM_CHUNKS) {
            int ns = (stage + 2 >= 3) ? stage - 1 : stage + 2;
            gm_load_stage(sb + ns * GM_STAGE, a_hi, a_lo, b_hi, b_lo, (i + 2) * 32, tid);
            cp_commit();
        }
        uint32_t st = sb + stage * GM_STAGE;

#pragma unroll
        for (int ks = 0; ks < 2; ks++) {
            uint32_t koff = ks * 32;
            uint32_t fah[4][4], fal[4][4];
#pragma unroll
            for (int mt = 0; mt < 4; mt++) {
                ldsm_x4(fah[mt], st + aoff + koff + mt * 16 * GM_ROWB);
                ldsm_x4(fal[mt], st + GM_A_ARR + aoff + koff + mt * 16 * GM_ROWB);
            }
#pragma unroll
            for (int np = 0; np < 4; np++) {
                uint32_t fbh[4], fbl[4];
                ldsm_x4(fbh, st + 2 * GM_A_ARR + boff + koff + np * 16 * GM_ROWB);
                ldsm_x4(fbl, st + 2 * GM_A_ARR + GM_B_ARR + boff + koff + np * 16 * GM_ROWB);
#pragma unroll
                for (int mt = 0; mt < 4; mt++) {
#pragma unroll
                    for (int half = 0; half < 2; half++) {
                        float* cc = c[mt][np * 2 + half];
                        mma_bf16(cc, fah[mt], fbh + half * 2);
                        mma_bf16(cc, fal[mt], fbh + half * 2);
                        mma_bf16(cc, fah[mt], fbl + half * 2);
                    }
                }
            }
        }
        stage = (stage + 1 >= 3) ? 0 : stage + 1;
    }

    const int erow = bm + wm * 64 + (lane >> 2);
    const int ecol = bn + wn * 64 + (lane & 3) * 2;
#pragma unroll
    for (int mt = 0; mt < 4; mt++)
#pragma unroll
        for (int nt = 0; nt < 8; nt++) {
            int r0 = erow + mt * 16;
            int cc = ecol + (nt >> 1) * 16 + (nt & 1) * 8;
            *(float2*)&C[(size_t)r0 * D_ + cc]       = make_float2(c[mt][nt][0], c[mt][nt][1]);
            *(float2*)&C[(size_t)(r0 + 8) * D_ + cc] = make_float2(c[mt][nt][2], c[mt][nt][3]);
        }
}

// ---------------------------------------------------------------------------
// RoPE tables: fp64 pow on 16 threads only; table uses fp32 Cody-Waite + MUFU.
// ---------------------------------------------------------------------------
__global__ void rope_freq_kernel() {
    int j = threadIdx.x;
    if (j < 16) g_freqf[j] = (float)pow(1.0 / 1024.0, (double)j / 15.0);
}

__global__ __launch_bounds__(256) void rope_tables_kernel() {
    int i = blockIdx.x * blockDim.x + threadIdx.x;
    if (i >= T_ * 32) return;
    int t = i >> 5;
    int j = i & 31;
    if (j >= 16) { g_cos[i] = 1.0f; g_sin[i] = 0.0f; return; }
    float theta = (float)t * g_freqf[j];
    const float inv2pi = 0.15915494309189535f;
    const float c1 = 6.28125f;
    const float c2 = 1.9345283508300781e-3f;
    const float c3 = 7.7882876e-7f;
    float n = rintf(theta * inv2pi);
    float r = fmaf(-n, c1, theta);
    r = fmaf(-n, c2, r);
    r = fmaf(-n, c3, r);
    g_cos[i] = cosf(r);
    g_sin[i] = sinf(r);
}

// ---------------------------------------------------------------------------
// Fused per-head RMSNorm + RoPE; writes head-major bf16 hi/lo.
// Q scaled by 0.125 * log2(e): flash softmax runs in exp2 domain.
// ---------------------------------------------------------------------------
#define QSCALE (0.125f * 1.4426950408889634f)

__global__ __launch_bounds__(256) void norm_rope_kernel() {
    int gw   = (blockIdx.x * blockDim.x + threadIdx.x) >> 5;
    int lane = threadIdx.x & 31;
    if (gw >= NTOK * H_) return;

    int token = gw >> 4;
    int h = gw & 15;
    int b = token >> 11;
    int t = token & (T_ - 1);
    size_t base = (size_t)gw * 64;
    size_t hb = (((size_t)(b * H_ + h)) * T_ + t) * HD_;

    float c = g_cos[t * 32 + lane];
    float s = g_sin[t * 32 + lane];

    {   // Q
        float a  = g_q[base + lane];
        float b2 = g_q[base + lane + 32];
        float ss = a * a + b2 * b2;
#pragma unroll
        for (int m = 16; m > 0; m >>= 1) ss += __shfl_xor_sync(0xffffffffu, ss, m);
        float r = rsqrtf(ss * (1.0f / 64.0f) + 1e-6f);
        a *= r; b2 *= r;
        float y1 = (a * c + b2 * s) * QSCALE;
        float y2 = (-a * s + b2 * c) * QSCALE;
        __nv_bfloat16 h1 = __float2bfloat16(y1);
        __nv_bfloat16 h2 = __float2bfloat16(y2);
        g_qhi[hb + lane]      = h1;
        g_qhi[hb + lane + 32] = h2;
        g_qlo[hb + lane]      = __float2bfloat16(y1 - __bfloat162float(h1));
        g_qlo[hb + lane + 32] = __float2bfloat16(y2 - __bfloat162float(h2));
    }
    {   // K
        float a  = g_k[base + lane];
        float b2 = g_k[base + lane + 32];
        float ss = a * a + b2 * b2;
#pragma unroll
        for (int m = 16; m > 0; m >>= 1) ss += __shfl_xor_sync(0xffffffffu, ss, m);
        float r = rsqrtf(ss * (1.0f / 64.0f) + 1e-6f);
        a *= r; b2 *= r;
        float y1 = a * c + b2 * s;
        float y2 = -a * s + b2 * c;
        __nv_bfloat16 h1 = __float2bfloat16(y1);
        __nv_bfloat16 h2 = __float2bfloat16(y2);
        g_khi[hb + lane]      = h1;
        g_khi[hb + lane + 32] = h2;
        g_klo[hb + lane]      = __float2bfloat16(y1 - __bfloat162float(h1));
        g_klo[hb + lane + 32] = __float2bfloat16(y2 - __bfloat162float(h2));
    }
}

// ---------------------------------------------------------------------------
// Flash attention via mma.sync, bf16x3 (causal). 128x128 tiles, exp2 softmax.
// Epilogue writes bf16 hi/lo split directly (token-major) for the wo GEMM.
// ---------------------------------------------------------------------------
#define FROWB   144u
#define FQ_SIZE (128 * 144)
#define FKV_OFF (2 * FQ_SIZE)
#define FKV_ARR (128 * 144)
#define FSTAGE  (4 * FKV_ARR)
#define FMMA_SMEM (FKV_OFF + 2 * FSTAGE)   // 184320

__device__ __forceinline__ void f_load_kv(
    uint32_t dst, const __nv_bfloat16* kh, const __nv_bfloat16* kl,
    const __nv_bfloat16* vh, const __nv_bfloat16* vl, size_t goff, int tid)
{
    const __nv_bfloat16* srcs[4] = {kh, kl, vh, vl};
    int seg = tid & 7, r0 = tid >> 3;
#pragma unroll
    for (int arr = 0; arr < 4; arr++) {
        const __nv_bfloat16* s = srcs[arr] + goff + seg * 8;
        uint32_t d = dst + arr * FKV_ARR + seg * 16;
#pragma unroll
        for (int rr = 0; rr < 4; rr++) {
            int row = r0 + rr * 32;
            cp_async16(d + row * FROWB, s + row * HD_);
        }
    }
}

__global__ __launch_bounds__(256, 1) void flash_mma_kernel(
    const __nv_bfloat16* __restrict__ Qhi, const __nv_bfloat16* __restrict__ Qlo,
    const __nv_bfloat16* __restrict__ Khi, const __nv_bfloat16* __restrict__ Klo,
    const __nv_bfloat16* __restrict__ Vhi, const __nv_bfloat16* __restrict__ Vlo,
    __nv_bfloat16* __restrict__ Ohi, __nv_bfloat16* __restrict__ Olo)
{
    extern __shared__ __align__(128) char fsm[];
    uint32_t sb = smem_to_u32(fsm);
    const int tid = threadIdx.x, wid = tid >> 5, lane = tid & 31;
    const int bh = blockIdx.x;
    const int qt = 15 - blockIdx.y;
    const int b = bh >> 4, h = bh & 15;
    const size_t headoff = (size_t)bh * T_ * HD_;
    const int nkt = qt + 1;

    {
        int seg = tid & 7, r0 = tid >> 3;
        const __nv_bfloat16* q0 = Qhi + headoff + (size_t)qt * 128 * HD_ + seg * 8;
        const __nv_bfloat16* q1 = Qlo + headoff + (size_t)qt * 128 * HD_ + seg * 8;
#pragma unroll
        for (int rr = 0; rr < 4; rr++) {
            int row = r0 + rr * 32;
            cp_async16(sb + row * FROWB + seg * 16, q0 + row * HD_);
            cp_async16(sb + FQ_SIZE + row * FROWB + seg * 16, q1 + row * HD_);
        }
    }
    f_load_kv(sb + FKV_OFF, Khi, Klo, Vhi, Vlo, headoff, tid);
    cp_commit();

    uint32_t fqh[4][4], fql[4][4];
    float o[8][4];
#pragma unroll
    for (int nt = 0; nt < 8; nt++)
#pragma unroll
        for (int r = 0; r < 4; r++) o[nt][r] = 0.0f;
    float m0 = -1e30f, m1 = -1e30f, l0 = 0.0f, l1 = 0.0f;

    const uint32_t qrow_off = (uint32_t)(wid * 16 + (lane & 15)) * FROWB + (lane >> 4) * 16;
    const uint32_t krow_off = (uint32_t)((lane & 7) + ((lane >> 4) << 3)) * FROWB
                              + ((lane >> 3) & 1) * 16;
    const uint32_t vrow_off = (uint32_t)(lane & 15) * FROWB + (lane >> 4) * 16;

    for (int jt = 0; jt < nkt; jt++) {
        if (jt + 1 < nkt) {
            f_load_kv(sb + FKV_OFF + ((jt + 1) & 1) * FSTAGE, Khi, Klo, Vhi, Vlo,
                      headoff + (size_t)(jt + 1) * 128 * HD_, tid);
            cp_commit();
            cp_wait<1>();
        } else {
            cp_wait<0>();
        }
        __syncthreads();

        if (jt == 0) {
#pragma unroll
            for (int ks = 0; ks < 4; ks++) {
                ldsm_x4(fqh[ks], sb + qrow_off + ks * 32);
                ldsm_x4(fql[ks], sb + FQ_SIZE + qrow_off + ks * 32);
            }
        }

        uint32_t st = sb + FKV_OFF + (jt & 1) * FSTAGE;

        float s[16][4];
#pragma unroll
        for (int nt = 0; nt < 16; nt++)
#pragma unroll
            for (int r = 0; r < 4; r++) s[nt][r] = 0.0f;

#pragma unroll
        for (int np = 0; np < 8; np++) {
#pragma unroll
            for (int ks = 0; ks < 4; ks++) {
                uint32_t addr = st + krow_off + np * 16 * FROWB + ks * 32;
                uint32_t fk[4];
                ldsm_x4(fk, addr);
                mma_bf16(s[2 * np],     fqh[ks], fk + 0);
                mma_bf16(s[2 * np + 1], fqh[ks], fk + 2);
                mma_bf16(s[2 * np],     fql[ks], fk + 0);
                mma_bf16(s[2 * np + 1], fql[ks], fk + 2);
                ldsm_x4(fk, addr + FKV_ARR);
                mma_bf16(s[2 * np],     fqh[ks], fk + 0);
                mma_bf16(s[2 * np + 1], fqh[ks], fk + 2);
            }
        }

        if (jt == qt) {
            int grow = qt * 128 + wid * 16 + (lane >> 2);
            int gc0 = jt * 128 + (lane & 3) * 2;
#pragma unroll
            for (int nt = 0; nt < 16; nt++) {
                int cc = gc0 + nt * 8;
                if (cc > grow)          s[nt][0] = -1e30f;
                if (cc + 1 > grow)      s[nt][1] = -1e30f;
                if (cc > grow + 8)      s[nt][2] = -1e30f;
                if (cc + 1 > grow + 8)  s[nt][3] = -1e30f;
            }
        }

        float mx0 = -1e30f, mx1 = -1e30f;
#pragma unroll
        for (int nt = 0; nt < 16; nt++) {
            mx0 = fmaxf(mx0, fmaxf(s[nt][0], s[nt][1]));
            mx1 = fmaxf(mx1, fmaxf(s[nt][2], s[nt][3]));
        }
        mx0 = fmaxf(mx0, __shfl_xor_sync(0xffffffffu, mx0, 1));
        mx0 = fmaxf(mx0, __shfl_xor_sync(0xffffffffu, mx0, 2));
        mx1 = fmaxf(mx1, __shfl_xor_sync(0xffffffffu, mx1, 1));
        mx1 = fmaxf(mx1, __shfl_xor_sync(0xffffffffu, mx1, 2));
        float mn0 = fmaxf(m0, mx0), mn1 = fmaxf(m1, mx1);
        float al0 = exp2f(m0 - mn0), al1 = exp2f(m1 - mn1);
        float rs0 = 0.0f, rs1 = 0.0f;
#pragma unroll
        for (int nt = 0; nt < 16; nt++) {
            s[nt][0] = exp2f(s[nt][0] - mn0);
            s[nt][1] = exp2f(s[nt][1] - mn0);
            s[nt][2] = exp2f(s[nt][2] - mn1);
            s[nt][3] = exp2f(s[nt][3] - mn1);
            rs0 += s[nt][0] + s[nt][1];
            rs1 += s[nt][2] + s[nt][3];
        }
        rs0 += __shfl_xor_sync(0xffffffffu, rs0, 1);
        rs0 += __shfl_xor_sync(0xffffffffu, rs0, 2);
        rs1 += __shfl_xor_sync(0xffffffffu, rs1, 1);
        rs1 += __shfl_xor_sync(0xffffffffu, rs1, 2);
        l0 = l0 * al0 + rs0; m0 = mn0;
        l1 = l1 * al1 + rs1; m1 = mn1;
#pragma unroll
        for (int nt = 0; nt < 8; nt++) {
            o[nt][0] *= al0; o[nt][1] *= al0;
            o[nt][2] *= al1; o[nt][3] *= al1;
        }

        uint32_t fph[8][4], fpl[8][4];
#pragma unroll
        for (int f = 0; f < 8; f++) {
#pragma unroll
            for (int half = 0; half < 2; half++) {
                int nt = 2 * f + half;
#pragma unroll
                for (int rh = 0; rh < 2; rh++) {
                    float p0 = s[nt][rh * 2], p1 = s[nt][rh * 2 + 1];
                    uint32_t hi = pack_bf16x2(p0, p1);
                    float h0 = __uint_as_float(hi << 16);
                    float h1 = __uint_as_float(hi & 0xFFFF0000u);
                    uint32_t lo = pack_bf16x2(p0 - h0, p1 - h1);
                    fph[f][half * 2 + rh] = hi;
                    fpl[f][half * 2 + rh] = lo;
                }
            }
        }

#pragma unroll
        for (int nh = 0; nh < 4; nh++) {
#pragma unroll
            for (int ks = 0; ks < 8; ks++) {
                uint32_t addr = st + 2 * FKV_ARR + vrow_off + ks * 16 * FROWB + nh * 32;
                uint32_t fv[4];
                ldsm_x4_t(fv, addr);
                mma_bf16(o[2 * nh],     fph[ks], fv + 0);
                mma_bf16(o[2 * nh + 1], fph[ks], fv + 2);
                mma_bf16(o[2 * nh],     fpl[ks], fv + 0);
                mma_bf16(o[2 * nh + 1], fpl[ks], fv + 2);
                ldsm_x4_t(fv, addr + FKV_ARR);
                mma_bf16(o[2 * nh],     fph[ks], fv + 0);
                mma_bf16(o[2 * nh + 1], fph[ks], fv + 2);
            }
        }
        __syncthreads();
    }

    // epilogue: normalize + bf16 hi/lo split, token-major [b][t][h*64+hd]
    float inv0 = 1.0f / l0, inv1 = 1.0f / l1;
    int row = qt * 128 + wid * 16 + (lane >> 2);
    size_t base0 = ((size_t)b * T_ + row) * D_ + h * 64 + (lane & 3) * 2;
    size_t base1 = base0 + (size_t)8 * D_;
#pragma unroll
    for (int nt = 0; nt < 8; nt++) {
        float v0 = o[nt][0] * inv0, v1 = o[nt][1] * inv0;
        float v2 = o[nt][2] * inv1, v3 = o[nt][3] * inv1;
        __nv_bfloat16 h0 = __float2bfloat16(v0), h1 = __float2bfloat16(v1);
        __nv_bfloat16 h2 = __float2bfloat16(v2), h3 = __float2bfloat16(v3);
        *reinterpret_cast<__nv_bfloat162*>(Ohi + base0 + nt * 8) = __nv_bfloat162(h0, h1);
        *reinterpret_cast<__nv_bfloat162*>(Ohi + base1 + nt * 8) = __nv_bfloat162(h2, h3);
        *reinterpret_cast<__nv_bfloat162*>(Olo + base0 + nt * 8) = __nv_bfloat162(
            __float2bfloat16(v0 - __bfloat162float(h0)),
            __float2bfloat16(v1 - __bfloat162float(h1)));
        *reinterpret_cast<__nv_bfloat162*>(Olo + base1 + nt * 8) = __nv_bfloat162(
            __float2bfloat16(v2 - __bfloat162float(h2)),
            __float2bfloat16(v3 - __bfloat162float(h3)));
    }
}

// ---------------------------------------------------------------------------
// Launch
// ---------------------------------------------------------------------------
extern "C" void kernel_launch(void* const* d_in, const int* in_sizes, int n_in,
                              void* d_out, int out_size)
{
    (void)in_sizes; (void)n_in; (void)out_size;
    const float* x  = (const float*)d_in[0];
    const float* w[4] = {(const float*)d_in[1], (const float*)d_in[2],
                         (const float*)d_in[3], (const float*)d_in[4]};
    float* out = (float*)d_out;

    float *qp, *kp, *vp;
    __nv_bfloat16 *ahi, *alo, *whi, *wlo;
    __nv_bfloat16 *qhi, *qlo, *khi, *klo, *vhi, *vlo;
    cudaGetSymbolAddress((void**)&qp, g_q);
    cudaGetSymbolAddress((void**)&kp, g_k);
    cudaGetSymbolAddress((void**)&vp, g_v);
    cudaGetSymbolAddress((void**)&ahi, g_ahi);
    cudaGetSymbolAddress((void**)&alo, g_alo);
    cudaGetSymbolAddress((void**)&whi, g_whi);
    cudaGetSymbolAddress((void**)&wlo, g_wlo);
    cudaGetSymbolAddress((void**)&qhi, g_qhi);
    cudaGetSymbolAddress((void**)&qlo, g_qlo);
    cudaGetSymbolAddress((void**)&khi, g_khi);
    cudaGetSymbolAddress((void**)&klo, g_klo);
    cudaGetSymbolAddress((void**)&vhi, g_vhi);
    cudaGetSymbolAddress((void**)&vlo, g_vlo);

    cudaFuncSetAttribute(gemm_mma_kernel,
                         cudaFuncAttributeMaxDynamicSharedMemorySize, GM_SMEM);
    cudaFuncSetAttribute(flash_mma_kernel,
                         cudaFuncAttributeMaxDynamicSharedMemorySize, FMMA_SMEM);

    rope_freq_kernel<<<1, 16>>>();
    rope_tables_kernel<<<(T_ * 32 + 255) / 256, 256>>>();

    split_kernel<<<(NTOK * D_ / 4 + 255) / 256, 256>>>(x, ahi, alo, NTOK * D_);
    split_w_kernel<<<(4 * D_ * D_ / 4 + 255) / 256, 256>>>(
        w[0], w[1], w[2], w[3], whi, wlo);

    gemm_mma_kernel<<<dim3(D_ / 128, NTOK / 256, 3), 256, GM_SMEM>>>(
        ahi, alo, whi, wlo, 0, qp, kp, vp);

    norm_rope_kernel<<<(NTOK * H_) / 8, 256>>>();
    split_v_kernel<<<(NTOK * D_ / 4 + 255) / 256, 256>>>();

    // flash writes bf16 hi/lo attention output directly into the A buffers
    flash_mma_kernel<<<dim3(BH_, T_ / 128), 256, FMMA_SMEM>>>(
        qhi, qlo, khi, klo, vhi, vlo, ahi, alo);

    gemm_mma_kernel<<<dim3(D_ / 128, NTOK / 256, 1), 256, GM_SMEM>>>(
        ahi, alo, whi, wlo, 3, out, out, out);
}

// round 9
// speedup vs baseline: 1.6150x; 1.0567x over previous
#include <cuda_runtime.h>
#include <cuda_bf16.h>
#include <math.h>
#include <stdint.h>

// Problem constants
#define B_   4
#define T_   2048
#define D_   1024
#define H_   16
#define HD_  64
#define NTOK (B_ * T_)   // 8192
#define BH_  (B_ * H_)   // 64

// ---------------------------------------------------------------------------
// Scratch (device globals: allocation-free rule)
// ---------------------------------------------------------------------------
__device__ float g_q[NTOK * D_];
__device__ float g_k[NTOK * D_];
__device__ float g_cos[T_ * 32];
__device__ float g_sin[T_ * 32];
__device__ float g_freqf[16];

// bf16 hi/lo splits for projection GEMMs (A buffers reused: x, then attn out)
__device__ __nv_bfloat16 g_ahi[NTOK * D_];
__device__ __nv_bfloat16 g_alo[NTOK * D_];
__device__ __nv_bfloat16 g_whi[4][D_ * D_];
__device__ __nv_bfloat16 g_wlo[4][D_ * D_];

// head-major bf16 hi/lo for flash attention: [bh][T][HD]
__device__ __nv_bfloat16 g_qhi[BH_ * T_ * HD_];
__device__ __nv_bfloat16 g_qlo[BH_ * T_ * HD_];
__device__ __nv_bfloat16 g_khi[BH_ * T_ * HD_];
__device__ __nv_bfloat16 g_klo[BH_ * T_ * HD_];
__device__ __nv_bfloat16 g_vhi[BH_ * T_ * HD_];
__device__ __nv_bfloat16 g_vlo[BH_ * T_ * HD_];

// ---------------------------------------------------------------------------
// PTX helpers (base compute_103 target: mma.sync / ldmatrix / cp.async only)
// ---------------------------------------------------------------------------
__device__ __forceinline__ uint32_t smem_to_u32(const void* p) {
    uint32_t a;
    asm("{ .reg .u64 t; cvta.to.shared.u64 t, %1; cvt.u32.u64 %0, t; }"
        : "=r"(a) : "l"(p));
    return a;
}

__device__ __forceinline__ void ldsm_x4(uint32_t* r, uint32_t addr) {
    asm volatile("ldmatrix.sync.aligned.m8n8.x4.shared.b16 {%0,%1,%2,%3}, [%4];"
                 : "=r"(r[0]), "=r"(r[1]), "=r"(r[2]), "=r"(r[3]) : "r"(addr));
}

__device__ __forceinline__ void ldsm_x4_t(uint32_t* r, uint32_t addr) {
    asm volatile("ldmatrix.sync.aligned.m8n8.x4.trans.shared.b16 {%0,%1,%2,%3}, [%4];"
                 : "=r"(r[0]), "=r"(r[1]), "=r"(r[2]), "=r"(r[3]) : "r"(addr));
}

__device__ __forceinline__ void mma_bf16(float* c, const uint32_t* a, const uint32_t* b) {
    asm volatile(
        "mma.sync.aligned.m16n8k16.row.col.f32.bf16.bf16.f32 "
        "{%0,%1,%2,%3}, {%4,%5,%6,%7}, {%8,%9}, {%0,%1,%2,%3};"
        : "+f"(c[0]), "+f"(c[1]), "+f"(c[2]), "+f"(c[3])
        : "r"(a[0]), "r"(a[1]), "r"(a[2]), "r"(a[3]), "r"(b[0]), "r"(b[1]));
}

__device__ __forceinline__ void cp_async16(uint32_t dst, const void* src) {
    asm volatile("cp.async.cg.shared.global [%0], [%1], 16;"
                 :: "r"(dst), "l"(src));
}
__device__ __forceinline__ void cp_commit() {
    asm volatile("cp.async.commit_group;" ::: "memory");
}
template <int N>
__device__ __forceinline__ void cp_wait() {
    asm volatile("cp.async.wait_group %0;" :: "n"(N) : "memory");
}

__device__ __forceinline__ uint32_t pack_bf16x2(float lo, float hi) {
    uint32_t r;
    asm("cvt.rn.bf16x2.f32 %0, %1, %2;" : "=r"(r) : "f"(hi), "f"(lo));
    return r;
}

// ---------------------------------------------------------------------------
// fp32 -> (bf16 hi, bf16 lo) split (flat layout)
// ---------------------------------------------------------------------------
__global__ __launch_bounds__(256) void split_kernel(
    const float* __restrict__ src, __nv_bfloat16* __restrict__ hi,
    __nv_bfloat16* __restrict__ lo, int n)
{
    int i4 = (blockIdx.x * blockDim.x + threadIdx.x) * 4;
    if (i4 >= n) return;
    float4 v = *(const float4*)(src + i4);
    __nv_bfloat16 h0 = __float2bfloat16(v.x);
    __nv_bfloat16 h1 = __float2bfloat16(v.y);
    __nv_bfloat16 h2 = __float2bfloat16(v.z);
    __nv_bfloat16 h3 = __float2bfloat16(v.w);
    reinterpret_cast<__nv_bfloat162*>(hi + i4)[0] = __nv_bfloat162(h0, h1);
    reinterpret_cast<__nv_bfloat162*>(hi + i4)[1] = __nv_bfloat162(h2, h3);
    reinterpret_cast<__nv_bfloat162*>(lo + i4)[0] = __nv_bfloat162(
        __float2bfloat16(v.x - __bfloat162float(h0)),
        __float2bfloat16(v.y - __bfloat162float(h1)));
    reinterpret_cast<__nv_bfloat162*>(lo + i4)[1] = __nv_bfloat162(
        __float2bfloat16(v.z - __bfloat162float(h2)),
        __float2bfloat16(v.w - __bfloat162float(h3)));
}

// All 4 weights in one launch
__global__ __launch_bounds__(256) void split_w_kernel(
    const float* __restrict__ w0, const float* __restrict__ w1,
    const float* __restrict__ w2, const float* __restrict__ w3,
    __nv_bfloat16* __restrict__ hi, __nv_bfloat16* __restrict__ lo)
{
    int i4 = (blockIdx.x * blockDim.x + threadIdx.x) * 4;
    if (i4 >= 4 * D_ * D_) return;
    int wi = i4 >> 20;
    int off = i4 & (D_ * D_ - 1);
    const float* src = (wi == 0) ? w0 : (wi == 1) ? w1 : (wi == 2) ? w2 : w3;
    float4 v = *(const float4*)(src + off);
    __nv_bfloat16 h0 = __float2bfloat16(v.x);
    __nv_bfloat16 h1 = __float2bfloat16(v.y);
    __nv_bfloat16 h2 = __float2bfloat16(v.z);
    __nv_bfloat16 h3 = __float2bfloat16(v.w);
    reinterpret_cast<__nv_bfloat162*>(hi + i4)[0] = __nv_bfloat162(h0, h1);
    reinterpret_cast<__nv_bfloat162*>(hi + i4)[1] = __nv_bfloat162(h2, h3);
    reinterpret_cast<__nv_bfloat162*>(lo + i4)[0] = __nv_bfloat162(
        __float2bfloat16(v.x - __bfloat162float(h0)),
        __float2bfloat16(v.y - __bfloat162float(h1)));
    reinterpret_cast<__nv_bfloat162*>(lo + i4)[1] = __nv_bfloat162(
        __float2bfloat16(v.z - __bfloat162float(h2)),
        __float2bfloat16(v.w - __bfloat162float(h3)));
}

// ---------------------------------------------------------------------------
// mma.sync GEMM, bf16x3 split: C[8192,1024] = A @ W^T
// Flash-mirror cadence: CTA 256x128, 8 warps (4x2) of 64x64, BK=64,
// 2-stage ring with 144B-strided rows, 384 mma/warp between syncs.
// z==2 (V projection) writes head-major bf16 hi/lo directly.
// ---------------------------------------------------------------------------
#define GM_ROWB   144u
#define GM_A_ARR  (256 * 144)                    // 36864
#define GM_B_ARR  (128 * 144)                    // 18432
#define GM_STAGE  (2 * GM_A_ARR + 2 * GM_B_ARR)  // 110592
#define GM_SMEM   (2 * GM_STAGE)                 // 221184
#define GM_CHUNKS 16                             // K chunks of 64

__device__ __forceinline__ void gm_load_stage(
    uint32_t sbase, const __nv_bfloat16* a_hi, const __nv_bfloat16* a_lo,
    const __nv_bfloat16* b_hi, const __nv_bfloat16* b_lo, int k0, int tid)
{
    int seg = tid & 7;            // 16B segment within 128B row payload
    int r0  = tid >> 3;           // 0..31
    const __nv_bfloat16* ah = a_hi + k0 + seg * 8;
    const __nv_bfloat16* al = a_lo + k0 + seg * 8;
    const __nv_bfloat16* bh = b_hi + k0 + seg * 8;
    const __nv_bfloat16* bl = b_lo + k0 + seg * 8;
    uint32_t d0 = sbase + seg * 16;
#pragma unroll
    for (int rr = 0; rr < 8; rr++) {
        int row = r0 + rr * 32;
        cp_async16(d0 + row * GM_ROWB, ah + (size_t)row * D_);
        cp_async16(d0 + GM_A_ARR + row * GM_ROWB, al + (size_t)row * D_);
    }
#pragma unroll
    for (int rr = 0; rr < 4; rr++) {
        int row = r0 + rr * 32;
        cp_async16(d0 + 2 * GM_A_ARR + row * GM_ROWB, bh + (size_t)row * D_);
        cp_async16(d0 + 2 * GM_A_ARR + GM_B_ARR + row * GM_ROWB, bl + (size_t)row * D_);
    }
}

__global__ __launch_bounds__(256, 1) void gemm_mma_kernel(
    const __nv_bfloat16* __restrict__ Ahi, const __nv_bfloat16* __restrict__ Alo,
    const __nv_bfloat16* __restrict__ Whi, const __nv_bfloat16* __restrict__ Wlo,
    int wbase, float* C0, float* C1)
{
    extern __shared__ __align__(128) char smem[];
    uint32_t sb = smem_to_u32(smem);

    const int tid  = threadIdx.x;
    const int wid  = tid >> 5;
    const int lane = tid & 31;
    const int wm = wid & 3;
    const int wn = wid >> 2;
    const int bm = blockIdx.y * 256;
    const int bn = blockIdx.x * 128;
    const int z  = blockIdx.z;

    const __nv_bfloat16* a_hi = Ahi + (size_t)bm * D_;
    const __nv_bfloat16* a_lo = Alo + (size_t)bm * D_;
    const __nv_bfloat16* b_hi = Whi + (size_t)(wbase + z) * D_ * D_ + (size_t)bn * D_;
    const __nv_bfloat16* b_lo = Wlo + (size_t)(wbase + z) * D_ * D_ + (size_t)bn * D_;

    float c[4][8][4];
#pragma unroll
    for (int mt = 0; mt < 4; mt++)
#pragma unroll
        for (int nt = 0; nt < 8; nt++)
#pragma unroll
            for (int r = 0; r < 4; r++) c[mt][nt][r] = 0.0f;

    const int rowA = lane & 15;
    const int kbA  = lane >> 4;
    const int rowB = (lane & 7) + ((lane >> 4) << 3);
    const int kbB  = (lane >> 3) & 1;
    const uint32_t aoff = (uint32_t)(wm * 64 + rowA) * GM_ROWB + kbA * 16;
    const uint32_t boff = (uint32_t)(wn * 64 + rowB) * GM_ROWB + kbB * 16;

    // prologue: single stage in flight (flash-mirror)
    gm_load_stage(sb, a_hi, a_lo, b_hi, b_lo, 0, tid);
    cp_commit();

    for (int i = 0; i < GM_CHUNKS; i++) {
        if (i + 1 < GM_CHUNKS) {
            gm_load_stage(sb + ((i + 1) & 1) * GM_STAGE, a_hi, a_lo, b_hi, b_lo,
                          (i + 1) * 64, tid);
            cp_commit();
            cp_wait<1>();
        } else {
            cp_wait<0>();
        }
        __syncthreads();

        uint32_t st = sb + (i & 1) * GM_STAGE;
#pragma unroll
        for (int ks = 0; ks < 4; ks++) {
            uint32_t koff = ks * 32;
            uint32_t fah[4][4], fal[4][4];
#pragma unroll
            for (int mt = 0; mt < 4; mt++) {
                ldsm_x4(fah[mt], st + aoff + koff + mt * 16 * GM_ROWB);
                ldsm_x4(fal[mt], st + GM_A_ARR + aoff + koff + mt * 16 * GM_ROWB);
            }
#pragma unroll
            for (int np = 0; np < 4; np++) {
                uint32_t fbh[4], fbl[4];
                ldsm_x4(fbh, st + 2 * GM_A_ARR + boff + koff + np * 16 * GM_ROWB);
                ldsm_x4(fbl, st + 2 * GM_A_ARR + GM_B_ARR + boff + koff + np * 16 * GM_ROWB);
#pragma unroll
                for (int mt = 0; mt < 4; mt++) {
#pragma unroll
                    for (int half = 0; half < 2; half++) {
                        float* cc = c[mt][np * 2 + half];
                        mma_bf16(cc, fah[mt], fbh + half * 2);
                        mma_bf16(cc, fal[mt], fbh + half * 2);
                        mma_bf16(cc, fah[mt], fbl + half * 2);
                    }
                }
            }
        }
        __syncthreads();
    }

    const int erow = bm + wm * 64 + (lane >> 2);
    const int ecol = bn + wn * 64 + (lane & 3) * 2;

    if (z == 2) {
        // V projection: write head-major bf16 hi/lo directly
#pragma unroll
        for (int mt = 0; mt < 4; mt++)
#pragma unroll
            for (int nt = 0; nt < 8; nt++) {
                int cc = ecol + (nt >> 1) * 16 + (nt & 1) * 8;
                int h = cc >> 6, hd = cc & 63;
#pragma unroll
                for (int rh = 0; rh < 2; rh++) {
                    int token = erow + mt * 16 + rh * 8;
                    int b = token >> 11, t = token & (T_ - 1);
                    size_t oi = (((size_t)(b * H_ + h)) * T_ + t) * HD_ + hd;
                    float v0 = c[mt][nt][rh * 2], v1 = c[mt][nt][rh * 2 + 1];
                    __nv_bfloat16 h0 = __float2bfloat16(v0);
                    __nv_bfloat16 h1 = __float2bfloat16(v1);
                    *reinterpret_cast<__nv_bfloat162*>(g_vhi + oi) = __nv_bfloat162(h0, h1);
                    *reinterpret_cast<__nv_bfloat162*>(g_vlo + oi) = __nv_bfloat162(
                        __float2bfloat16(v0 - __bfloat162float(h0)),
                        __float2bfloat16(v1 - __bfloat162float(h1)));
                }
            }
    } else {
        float* C = (z == 0) ? C0 : C1;
#pragma unroll
        for (int mt = 0; mt < 4; mt++)
#pragma unroll
            for (int nt = 0; nt < 8; nt++) {
                int r0 = erow + mt * 16;
                int cc = ecol + (nt >> 1) * 16 + (nt & 1) * 8;
                *(float2*)&C[(size_t)r0 * D_ + cc]       = make_float2(c[mt][nt][0], c[mt][nt][1]);
                *(float2*)&C[(size_t)(r0 + 8) * D_ + cc] = make_float2(c[mt][nt][2], c[mt][nt][3]);
            }
    }
}

// ---------------------------------------------------------------------------
// RoPE tables: fp64 pow on 16 threads only; table uses fp32 Cody-Waite + MUFU.
// ---------------------------------------------------------------------------
__global__ void rope_freq_kernel() {
    int j = threadIdx.x;
    if (j < 16) g_freqf[j] = (float)pow(1.0 / 1024.0, (double)j / 15.0);
}

__global__ __launch_bounds__(256) void rope_tables_kernel() {
    int i = blockIdx.x * blockDim.x + threadIdx.x;
    if (i >= T_ * 32) return;
    int t = i >> 5;
    int j = i & 31;
    if (j >= 16) { g_cos[i] = 1.0f; g_sin[i] = 0.0f; return; }
    float theta = (float)t * g_freqf[j];
    const float inv2pi = 0.15915494309189535f;
    const float c1 = 6.28125f;
    const float c2 = 1.9345283508300781e-3f;
    const float c3 = 7.7882876e-7f;
    float n = rintf(theta * inv2pi);
    float r = fmaf(-n, c1, theta);
    r = fmaf(-n, c2, r);
    r = fmaf(-n, c3, r);
    g_cos[i] = cosf(r);
    g_sin[i] = sinf(r);
}

// ---------------------------------------------------------------------------
// Fused per-head RMSNorm + RoPE; writes head-major bf16 hi/lo.
// Q scaled by 0.125 * log2(e): flash softmax runs in exp2 domain.
// ---------------------------------------------------------------------------
#define QSCALE (0.125f * 1.4426950408889634f)

__global__ __launch_bounds__(256) void norm_rope_kernel() {
    int gw   = (blockIdx.x * blockDim.x + threadIdx.x) >> 5;
    int lane = threadIdx.x & 31;
    if (gw >= NTOK * H_) return;

    int token = gw >> 4;
    int h = gw & 15;
    int b = token >> 11;
    int t = token & (T_ - 1);
    size_t base = (size_t)gw * 64;
    size_t hb = (((size_t)(b * H_ + h)) * T_ + t) * HD_;

    float c = g_cos[t * 32 + lane];
    float s = g_sin[t * 32 + lane];

    {   // Q
        float a  = g_q[base + lane];
        float b2 = g_q[base + lane + 32];
        float ss = a * a + b2 * b2;
#pragma unroll
        for (int m = 16; m > 0; m >>= 1) ss += __shfl_xor_sync(0xffffffffu, ss, m);
        float r = rsqrtf(ss * (1.0f / 64.0f) + 1e-6f);
        a *= r; b2 *= r;
        float y1 = (a * c + b2 * s) * QSCALE;
        float y2 = (-a * s + b2 * c) * QSCALE;
        __nv_bfloat16 h1 = __float2bfloat16(y1);
        __nv_bfloat16 h2 = __float2bfloat16(y2);
        g_qhi[hb + lane]      = h1;
        g_qhi[hb + lane + 32] = h2;
        g_qlo[hb + lane]      = __float2bfloat16(y1 - __bfloat162float(h1));
        g_qlo[hb + lane + 32] = __float2bfloat16(y2 - __bfloat162float(h2));
    }
    {   // K
        float a  = g_k[base + lane];
        float b2 = g_k[base + lane + 32];
        float ss = a * a + b2 * b2;
#pragma unroll
        for (int m = 16; m > 0; m >>= 1) ss += __shfl_xor_sync(0xffffffffu, ss, m);
        float r = rsqrtf(ss * (1.0f / 64.0f) + 1e-6f);
        a *= r; b2 *= r;
        float y1 = a * c + b2 * s;
        float y2 = -a * s + b2 * c;
        __nv_bfloat16 h1 = __float2bfloat16(y1);
        __nv_bfloat16 h2 = __float2bfloat16(y2);
        g_khi[hb + lane]      = h1;
        g_khi[hb + lane + 32] = h2;
        g_klo[hb + lane]      = __float2bfloat16(y1 - __bfloat162float(h1));
        g_klo[hb + lane + 32] = __float2bfloat16(y2 - __bfloat162float(h2));
    }
}

// ---------------------------------------------------------------------------
// Flash attention via mma.sync, bf16x3 (causal). 128x128 tiles, exp2 softmax.
// Epilogue writes bf16 hi/lo split directly (token-major) for the wo GEMM.
// ---------------------------------------------------------------------------
#define FROWB   144u
#define FQ_SIZE (128 * 144)
#define FKV_OFF (2 * FQ_SIZE)
#define FKV_ARR (128 * 144)
#define FSTAGE  (4 * FKV_ARR)
#define FMMA_SMEM (FKV_OFF + 2 * FSTAGE)   // 184320

__device__ __forceinline__ void f_load_kv(
    uint32_t dst, const __nv_bfloat16* kh, const __nv_bfloat16* kl,
    const __nv_bfloat16* vh, const __nv_bfloat16* vl, size_t goff, int tid)
{
    const __nv_bfloat16* srcs[4] = {kh, kl, vh, vl};
    int seg = tid & 7, r0 = tid >> 3;
#pragma unroll
    for (int arr = 0; arr < 4; arr++) {
        const __nv_bfloat16* s = srcs[arr] + goff + seg * 8;
        uint32_t d = dst + arr * FKV_ARR + seg * 16;
#pragma unroll
        for (int rr = 0; rr < 4; rr++) {
            int row = r0 + rr * 32;
            cp_async16(d + row * FROWB, s + row * HD_);
        }
    }
}

__global__ __launch_bounds__(256, 1) void flash_mma_kernel(
    const __nv_bfloat16* __restrict__ Qhi, const __nv_bfloat16* __restrict__ Qlo,
    const __nv_bfloat16* __restrict__ Khi, const __nv_bfloat16* __restrict__ Klo,
    const __nv_bfloat16* __restrict__ Vhi, const __nv_bfloat16* __restrict__ Vlo,
    __nv_bfloat16* __restrict__ Ohi, __nv_bfloat16* __restrict__ Olo)
{
    extern __shared__ __align__(128) char fsm[];
    uint32_t sb = smem_to_u32(fsm);
    const int tid = threadIdx.x, wid = tid >> 5, lane = tid & 31;
    const int bh = blockIdx.x;
    const int qt = 15 - blockIdx.y;
    const int b = bh >> 4, h = bh & 15;
    const size_t headoff = (size_t)bh * T_ * HD_;
    const int nkt = qt + 1;

    {
        int seg = tid & 7, r0 = tid >> 3;
        const __nv_bfloat16* q0 = Qhi + headoff + (size_t)qt * 128 * HD_ + seg * 8;
        const __nv_bfloat16* q1 = Qlo + headoff + (size_t)qt * 128 * HD_ + seg * 8;
#pragma unroll
        for (int rr = 0; rr < 4; rr++) {
            int row = r0 + rr * 32;
            cp_async16(sb + row * FROWB + seg * 16, q0 + row * HD_);
            cp_async16(sb + FQ_SIZE + row * FROWB + seg * 16, q1 + row * HD_);
        }
    }
    f_load_kv(sb + FKV_OFF, Khi, Klo, Vhi, Vlo, headoff, tid);
    cp_commit();

    uint32_t fqh[4][4], fql[4][4];
    float o[8][4];
#pragma unroll
    for (int nt = 0; nt < 8; nt++)
#pragma unroll
        for (int r = 0; r < 4; r++) o[nt][r] = 0.0f;
    float m0 = -1e30f, m1 = -1e30f, l0 = 0.0f, l1 = 0.0f;

    const uint32_t qrow_off = (uint32_t)(wid * 16 + (lane & 15)) * FROWB + (lane >> 4) * 16;
    const uint32_t krow_off = (uint32_t)((lane & 7) + ((lane >> 4) << 3)) * FROWB
                              + ((lane >> 3) & 1) * 16;
    const uint32_t vrow_off = (uint32_t)(lane & 15) * FROWB + (lane >> 4) * 16;

    for (int jt = 0; jt < nkt; jt++) {
        if (jt + 1 < nkt) {
            f_load_kv(sb + FKV_OFF + ((jt + 1) & 1) * FSTAGE, Khi, Klo, Vhi, Vlo,
                      headoff + (size_t)(jt + 1) * 128 * HD_, tid);
            cp_commit();
            cp_wait<1>();
        } else {
            cp_wait<0>();
        }
        __syncthreads();

        if (jt == 0) {
#pragma unroll
            for (int ks = 0; ks < 4; ks++) {
                ldsm_x4(fqh[ks], sb + qrow_off + ks * 32);
                ldsm_x4(fql[ks], sb + FQ_SIZE + qrow_off + ks * 32);
            }
        }

        uint32_t st = sb + FKV_OFF + (jt & 1) * FSTAGE;

        float s[16][4];
#pragma unroll
        for (int nt = 0; nt < 16; nt++)
#pragma unroll
            for (int r = 0; r < 4; r++) s[nt][r] = 0.0f;

#pragma unroll
        for (int np = 0; np < 8; np++) {
#pragma unroll
            for (int ks = 0; ks < 4; ks++) {
                uint32_t addr = st + krow_off + np * 16 * FROWB + ks * 32;
                uint32_t fk[4];
                ldsm_x4(fk, addr);
                mma_bf16(s[2 * np],     fqh[ks], fk + 0);
                mma_bf16(s[2 * np + 1], fqh[ks], fk + 2);
                mma_bf16(s[2 * np],     fql[ks], fk + 0);
                mma_bf16(s[2 * np + 1], fql[ks], fk + 2);
                ldsm_x4(fk, addr + FKV_ARR);
                mma_bf16(s[2 * np],     fqh[ks], fk + 0);
                mma_bf16(s[2 * np + 1], fqh[ks], fk + 2);
            }
        }

        if (jt == qt) {
            int grow = qt * 128 + wid * 16 + (lane >> 2);
            int gc0 = jt * 128 + (lane & 3) * 2;
#pragma unroll
            for (int nt = 0; nt < 16; nt++) {
                int cc = gc0 + nt * 8;
                if (cc > grow)          s[nt][0] = -1e30f;
                if (cc + 1 > grow)      s[nt][1] = -1e30f;
                if (cc > grow + 8)      s[nt][2] = -1e30f;
                if (cc + 1 > grow + 8)  s[nt][3] = -1e30f;
            }
        }

        float mx0 = -1e30f, mx1 = -1e30f;
#pragma unroll
        for (int nt = 0; nt < 16; nt++) {
            mx0 = fmaxf(mx0, fmaxf(s[nt][0], s[nt][1]));
            mx1 = fmaxf(mx1, fmaxf(s[nt][2], s[nt][3]));
        }
        mx0 = fmaxf(mx0, __shfl_xor_sync(0xffffffffu, mx0, 1));
        mx0 = fmaxf(mx0, __shfl_xor_sync(0xffffffffu, mx0, 2));
        mx1 = fmaxf(mx1, __shfl_xor_sync(0xffffffffu, mx1, 1));
        mx1 = fmaxf(mx1, __shfl_xor_sync(0xffffffffu, mx1, 2));
        float mn0 = fmaxf(m0, mx0), mn1 = fmaxf(m1, mx1);
        float al0 = exp2f(m0 - mn0), al1 = exp2f(m1 - mn1);
        float rs0 = 0.0f, rs1 = 0.0f;
#pragma unroll
        for (int nt = 0; nt < 16; nt++) {
            s[nt][0] = exp2f(s[nt][0] - mn0);
            s[nt][1] = exp2f(s[nt][1] - mn0);
            s[nt][2] = exp2f(s[nt][2] - mn1);
            s[nt][3] = exp2f(s[nt][3] - mn1);
            rs0 += s[nt][0] + s[nt][1];
            rs1 += s[nt][2] + s[nt][3];
        }
        rs0 += __shfl_xor_sync(0xffffffffu, rs0, 1);
        rs0 += __shfl_xor_sync(0xffffffffu, rs0, 2);
        rs1 += __shfl_xor_sync(0xffffffffu, rs1, 1);
        rs1 += __shfl_xor_sync(0xffffffffu, rs1, 2);
        l0 = l0 * al0 + rs0; m0 = mn0;
        l1 = l1 * al1 + rs1; m1 = mn1;
#pragma unroll
        for (int nt = 0; nt < 8; nt++) {
            o[nt][0] *= al0; o[nt][1] *= al0;
            o[nt][2] *= al1; o[nt][3] *= al1;
        }

        uint32_t fph[8][4], fpl[8][4];
#pragma unroll
        for (int f = 0; f < 8; f++) {
#pragma unroll
            for (int half = 0; half < 2; half++) {
                int nt = 2 * f + half;
#pragma unroll
                for (int rh = 0; rh < 2; rh++) {
                    float p0 = s[nt][rh * 2], p1 = s[nt][rh * 2 + 1];
                    uint32_t hi = pack_bf16x2(p0, p1);
                    float h0 = __uint_as_float(hi << 16);
                    float h1 = __uint_as_float(hi & 0xFFFF0000u);
                    uint32_t lo = pack_bf16x2(p0 - h0, p1 - h1);
                    fph[f][half * 2 + rh] = hi;
                    fpl[f][half * 2 + rh] = lo;
                }
            }
        }

#pragma unroll
        for (int nh = 0; nh < 4; nh++) {
#pragma unroll
            for (int ks = 0; ks < 8; ks++) {
                uint32_t addr = st + 2 * FKV_ARR + vrow_off + ks * 16 * FROWB + nh * 32;
                uint32_t fv[4];
                ldsm_x4_t(fv, addr);
                mma_bf16(o[2 * nh],     fph[ks], fv + 0);
                mma_bf16(o[2 * nh + 1], fph[ks], fv + 2);
                mma_bf16(o[2 * nh],     fpl[ks], fv + 0);
                mma_bf16(o[2 * nh + 1], fpl[ks], fv + 2);
                ldsm_x4_t(fv, addr + FKV_ARR);
                mma_bf16(o[2 * nh],     fph[ks], fv + 0);
                mma_bf16(o[2 * nh + 1], fph[ks], fv + 2);
            }
        }
        __syncthreads();
    }

    // epilogue: normalize + bf16 hi/lo split, token-major [b][t][h*64+hd]
    float inv0 = 1.0f / l0, inv1 = 1.0f / l1;
    int row = qt * 128 + wid * 16 + (lane >> 2);
    size_t base0 = ((size_t)b * T_ + row) * D_ + h * 64 + (lane & 3) * 2;
    size_t base1 = base0 + (size_t)8 * D_;
#pragma unroll
    for (int nt = 0; nt < 8; nt++) {
        float v0 = o[nt][0] * inv0, v1 = o[nt][1] * inv0;
        float v2 = o[nt][2] * inv1, v3 = o[nt][3] * inv1;
        __nv_bfloat16 h0 = __float2bfloat16(v0), h1 = __float2bfloat16(v1);
        __nv_bfloat16 h2 = __float2bfloat16(v2), h3 = __float2bfloat16(v3);
        *reinterpret_cast<__nv_bfloat162*>(Ohi + base0 + nt * 8) = __nv_bfloat162(h0, h1);
        *reinterpret_cast<__nv_bfloat162*>(Ohi + base1 + nt * 8) = __nv_bfloat162(h2, h3);
        *reinterpret_cast<__nv_bfloat162*>(Olo + base0 + nt * 8) = __nv_bfloat162(
            __float2bfloat16(v0 - __bfloat162float(h0)),
            __float2bfloat16(v1 - __bfloat162float(h1)));
        *reinterpret_cast<__nv_bfloat162*>(Olo + base1 + nt * 8) = __nv_bfloat162(
            __float2bfloat16(v2 - __bfloat162float(h2)),
            __float2bfloat16(v3 - __bfloat162float(h3)));
    }
}

// ---------------------------------------------------------------------------
// Launch
// ---------------------------------------------------------------------------
extern "C" void kernel_launch(void* const* d_in, const int* in_sizes, int n_in,
                              void* d_out, int out_size)
{
    (void)in_sizes; (void)n_in; (void)out_size;
    const float* x  = (const float*)d_in[0];
    const float* w[4] = {(const float*)d_in[1], (const float*)d_in[2],
                         (const float*)d_in[3], (const float*)d_in[4]};
    float* out = (float*)d_out;

    float *qp, *kp;
    __nv_bfloat16 *ahi, *alo, *whi, *wlo;
    __nv_bfloat16 *qhi, *qlo, *khi, *klo, *vhi, *vlo;
    cudaGetSymbolAddress((void**)&qp, g_q);
    cudaGetSymbolAddress((void**)&kp, g_k);
    cudaGetSymbolAddress((void**)&ahi, g_ahi);
    cudaGetSymbolAddress((void**)&alo, g_alo);
    cudaGetSymbolAddress((void**)&whi, g_whi);
    cudaGetSymbolAddress((void**)&wlo, g_wlo);
    cudaGetSymbolAddress((void**)&qhi, g_qhi);
    cudaGetSymbolAddress((void**)&qlo, g_qlo);
    cudaGetSymbolAddress((void**)&khi, g_khi);
    cudaGetSymbolAddress((void**)&klo, g_klo);
    cudaGetSymbolAddress((void**)&vhi, g_vhi);
    cudaGetSymbolAddress((void**)&vlo, g_vlo);

    cudaFuncSetAttribute(gemm_mma_kernel,
                         cudaFuncAttributeMaxDynamicSharedMemorySize, GM_SMEM);
    cudaFuncSetAttribute(flash_mma_kernel,
                         cudaFuncAttributeMaxDynamicSharedMemorySize, FMMA_SMEM);

    rope_freq_kernel<<<1, 16>>>();
    rope_tables_kernel<<<(T_ * 32 + 255) / 256, 256>>>();

    split_kernel<<<(NTOK * D_ / 4 + 255) / 256, 256>>>(x, ahi, alo, NTOK * D_);
    split_w_kernel<<<(4 * D_ * D_ / 4 + 255) / 256, 256>>>(
        w[0], w[1], w[2], w[3], whi, wlo);

    // fused Q/K/V projections; z==2 (V) writes head-major bf16 hi/lo directly
    gemm_mma_kernel<<<dim3(D_ / 128, NTOK / 256, 3), 256, GM_SMEM>>>(
        ahi, alo, whi, wlo, 0, qp, kp);

    norm_rope_kernel<<<(NTOK * H_) / 8, 256>>>();

    // flash writes bf16 hi/lo attention output directly into the A buffers
    flash_mma_kernel<<<dim3(BH_, T_ / 128), 256, FMMA_SMEM>>>(
        qhi, qlo, khi, klo, vhi, vlo, ahi, alo);

    gemm_mma_kernel<<<dim3(D_ / 128, NTOK / 256, 1), 256, GM_SMEM>>>(
        ahi, alo, whi, wlo, 3, out, out);
}